// round 6
// baseline (speedup 1.0000x reference)
#include <cuda_runtime.h>
#include <math.h>

#define T_STEPS 128
#define IN_D    512
#define H_D     512
#define B_D     256
#define TAG     64
#define LM_D    200
#define POS_D   6
#define CAP_D   3
#define HB      (H_D * B_D)
#define GATE_M  (4 * H_D)
#define TI_M    (3 * H_D)
#define NCTA    128

#define SEC_Y   ((size_t)B_D * T_STEPS * TAG)
#define OFF_LF  ((size_t)0)
#define OFF_LC  (SEC_Y)
#define OFF_YF  (2 * SEC_Y)
#define OFF_YC  (3 * SEC_Y)
#define OFF_TS  (4 * SEC_Y)

// ------------------------- scratch (device globals) -------------------------
__device__ float g_x    [(size_t)T_STEPS * IN_D   * B_D];
__device__ float g_pre  [(size_t)T_STEPS * GATE_M * B_D];
__device__ float g_tiC  [(size_t)T_STEPS * TI_M   * B_D];
__device__ float g_hall [(size_t)T_STEPS * H_D    * B_D];
__device__ float g_Ts   [(size_t)T_STEPS * H_D    * B_D];
__device__ float g_c    [HB];
__device__ float g_opre [HB];
__device__ unsigned g_barcnt;
// k-major weights
__device__ float g_wfT  [(size_t)H_D * GATE_M];
__device__ float g_wiiT [(size_t)IN_D * GATE_M];
__device__ float g_wtiT [(size_t)H_D * TI_M];
__device__ float g_whtT [(size_t)H_D * H_D];
__device__ float g_wcoT [(size_t)H_D * H_D];
__device__ float g_wlmtT[(size_t)LM_D * H_D];
__device__ float g_wpostT[(size_t)POS_D * H_D];
__device__ float g_wcaptT[(size_t)CAP_D * H_D];
__device__ float g_wyfT [(size_t)H_D * TAG];
__device__ float g_wycT [(size_t)H_D * TAG];
__device__ float g_AlmT [(size_t)LM_D * TI_M];
__device__ float g_AposT[(size_t)POS_D * TI_M];
__device__ float g_AcapT[(size_t)CAP_D * TI_M];
__device__ float g_vc   [TI_M];

__device__ __forceinline__ float sigm(float x) { return 1.f / (1.f + expf(-x)); }

// ---------------------------------------------------------------------------
// 64/32-tile GEMM core (same as R3). A k-major, B k-major.
// ---------------------------------------------------------------------------
template <int BM, int BN, int BK, int TM, int TN>
__device__ __forceinline__ void gk(const float* __restrict__ A,
                                   const float* __restrict__ B,
                                   int K, int ldA, int ldB, int m0, int n0,
                                   float (&acc)[TM][TN], float* sm)
{
    static_assert((BM / TM) * (BN / TN) == 256, "");
    float (*As)[BM] = (float (*)[BM])sm;
    float (*Bs)[BN] = (float (*)[BN])(sm + BK * BM);
    const int tid = threadIdx.x;
    const int tx = tid % (BN / TN), ty = tid / (BN / TN);
    constexpr int AV = BM / 4, BV = BN / 4;
    constexpr int AL = (BM * BK / 4) / 256, BL = (BN * BK / 4) / 256;
    const float4 z4 = make_float4(0.f, 0.f, 0.f, 0.f);

    for (int k0 = 0; k0 < K; k0 += BK) {
#pragma unroll
        for (int i = 0; i < AL; i++) {
            int li = tid + i * 256, k = li / AV, m4 = (li % AV) * 4;
            float4 v = (k0 + k < K) ? *(const float4*)&A[(size_t)(k0 + k) * ldA + m0 + m4] : z4;
            *(float4*)&As[k][m4] = v;
        }
#pragma unroll
        for (int i = 0; i < BL; i++) {
            int li = tid + i * 256, k = li / BV, n4 = (li % BV) * 4;
            float4 v = (k0 + k < K) ? *(const float4*)&B[(size_t)(k0 + k) * ldB + n0 + n4] : z4;
            *(float4*)&Bs[k][n4] = v;
        }
        __syncthreads();
#pragma unroll
        for (int k = 0; k < BK; k++) {
            float a[TM], b[TN];
            if constexpr (TM % 4 == 0) {
#pragma unroll
                for (int i = 0; i < TM; i += 4) {
                    float4 v = *(const float4*)&As[k][ty * TM + i];
                    a[i] = v.x; a[i+1] = v.y; a[i+2] = v.z; a[i+3] = v.w;
                }
            } else {
                float2 v = *(const float2*)&As[k][ty * TM];
                a[0] = v.x; a[1] = v.y;
            }
            if constexpr (TN == 4) {
                float4 v = *(const float4*)&Bs[k][tx * 4];
                b[0] = v.x; b[1] = v.y; b[2] = v.z; b[3] = v.w;
            } else {
                float2 v = *(const float2*)&Bs[k][tx * 2];
                b[0] = v.x; b[1] = v.y;
            }
#pragma unroll
            for (int i = 0; i < TM; i++)
#pragma unroll
                for (int j = 0; j < TN; j++) acc[i][j] += a[i] * b[j];
        }
        __syncthreads();
    }
}

// ---------------------------------------------------------------------------
// 128x128x16 core, TM=8 TN=8 (for the big parallel GEMMs). smem 16KB.
// ---------------------------------------------------------------------------
__device__ __forceinline__ void gk128(const float* __restrict__ A,
                                      const float* __restrict__ B,
                                      int K, int ldA, int ldB, int m0, int n0,
                                      float (&acc)[8][8], float* sm)
{
    float (*As)[128] = (float (*)[128])sm;
    float (*Bs)[128] = (float (*)[128])(sm + 16 * 128);
    const int tid = threadIdx.x;
    const int tx = tid % 16, ty = tid / 16;
    const float4 z4 = make_float4(0.f, 0.f, 0.f, 0.f);

    for (int k0 = 0; k0 < K; k0 += 16) {
#pragma unroll
        for (int i = 0; i < 2; i++) {
            int li = tid + i * 256, k = li / 32, m4 = (li % 32) * 4;
            float4 va = (k0 + k < K) ? *(const float4*)&A[(size_t)(k0 + k) * ldA + m0 + m4] : z4;
            *(float4*)&As[k][m4] = va;
            float4 vb = (k0 + k < K) ? *(const float4*)&B[(size_t)(k0 + k) * ldB + n0 + m4] : z4;
            *(float4*)&Bs[k][m4] = vb;
        }
        __syncthreads();
#pragma unroll
        for (int k = 0; k < 16; k++) {
            float a[8], b[8];
            float4 v0 = *(const float4*)&As[k][ty * 8];
            float4 v1 = *(const float4*)&As[k][ty * 8 + 4];
            a[0]=v0.x; a[1]=v0.y; a[2]=v0.z; a[3]=v0.w; a[4]=v1.x; a[5]=v1.y; a[6]=v1.z; a[7]=v1.w;
            float4 w0 = *(const float4*)&Bs[k][tx * 8];
            float4 w1 = *(const float4*)&Bs[k][tx * 8 + 4];
            b[0]=w0.x; b[1]=w0.y; b[2]=w0.z; b[3]=w0.w; b[4]=w1.x; b[5]=w1.y; b[6]=w1.z; b[7]=w1.w;
#pragma unroll
            for (int i = 0; i < 8; i++)
#pragma unroll
                for (int j = 0; j < 8; j++) acc[i][j] += a[i] * b[j];
        }
        __syncthreads();
    }
}

// --------------------------- one-time precompute ---------------------------
__global__ void k_tr(const float* __restrict__ in, float* __restrict__ out, int M, int K)
{
    __shared__ float tl[32][33];
    int k0 = blockIdx.x * 32, m0 = blockIdx.y * 32;
    int tx = threadIdx.x, ty = threadIdx.y;
    for (int i = ty; i < 32; i += 8)
        if (m0 + i < M && k0 + tx < K) tl[i][tx] = in[(size_t)(m0 + i) * K + k0 + tx];
    __syncthreads();
    for (int i = ty; i < 32; i += 8)
        if (k0 + i < K && m0 + tx < M) out[(size_t)(k0 + i) * M + m0 + tx] = tl[tx][i];
}

__global__ void k_permii(const float* __restrict__ w_ii)
{
    __shared__ float tl[32][33];
    int p0 = blockIdx.x * 32, k0 = blockIdx.y * 32;
    int tx = threadIdx.x, ty = threadIdx.y;
    for (int i = ty; i < 32; i += 8) {
        int p = p0 + i, m = (p & 3) * H_D + (p >> 2);
        tl[i][tx] = w_ii[(size_t)m * IN_D + k0 + tx];
    }
    __syncthreads();
    for (int i = ty; i < 32; i += 8)
        g_wiiT[(size_t)(k0 + i) * GATE_M + p0 + tx] = tl[tx][i];
}

__global__ void __launch_bounds__(256)
k_w2(const float* __restrict__ w_hi, const float* __restrict__ w_ht)
{
    __shared__ float sm[16 * 128];
    int n0 = blockIdx.x * 64, m0 = blockIdx.y * 64;
    float acc[4][4] = {};
    gk<64,64,16,4,4>(g_wtiT, w_ht, H_D, TI_M, H_D, m0, n0, acc, sm);
    int tx = threadIdx.x % 16, ty = threadIdx.x / 16;
#pragma unroll
    for (int i = 0; i < 4; i++) {
        int m = m0 + ty * 4 + i;
        int p = (m & 511) * 4 + (m >> 9);
#pragma unroll
        for (int j = 0; j < 4; j++) {
            int jc = n0 + tx * 4 + j;
            g_wfT[(size_t)jc * GATE_M + p] = acc[i][j] + w_hi[(size_t)m * H_D + jc];
        }
    }
}

__global__ void k_fillo(const float* __restrict__ w_hi)
{
    int idx = blockIdx.x * 256 + threadIdx.x;
    if (idx >= H_D * H_D) return;
    int r = idx >> 9, j = idx & 511;
    g_wfT[(size_t)j * GATE_M + 4 * r + 3] = w_hi[(size_t)(3 * H_D + r) * H_D + j];
}

__global__ void k_small(const float* __restrict__ w_lmt, const float* __restrict__ w_post,
                        const float* __restrict__ w_capt, const float* __restrict__ b_i)
{
    int idx = blockIdx.x * 256 + threadIdx.x;
    if (idx < TI_M * LM_D) {
        int l = idx / TI_M, m = idx % TI_M;
        float s = 0.f;
        for (int k = 0; k < H_D; k++) s += g_wtiT[(size_t)k * TI_M + m] * w_lmt[k * LM_D + l];
        g_AlmT[(size_t)l * TI_M + m] = s;
    } else if (idx < TI_M * (LM_D + POS_D)) {
        int q = idx - TI_M * LM_D, l = q / TI_M, m = q % TI_M;
        float s = 0.f;
        for (int k = 0; k < H_D; k++) s += g_wtiT[(size_t)k * TI_M + m] * w_post[k * POS_D + l];
        g_AposT[(size_t)l * TI_M + m] = s;
    } else if (idx < TI_M * (LM_D + POS_D + CAP_D)) {
        int q = idx - TI_M * (LM_D + POS_D), l = q / TI_M, m = q % TI_M;
        float s = 0.f;
        for (int k = 0; k < H_D; k++) s += g_wtiT[(size_t)k * TI_M + m] * w_capt[k * CAP_D + l];
        g_AcapT[(size_t)l * TI_M + m] = s;
    } else if (idx < TI_M * (LM_D + POS_D + CAP_D + 1)) {
        int m = idx - TI_M * (LM_D + POS_D + CAP_D);
        float s = 0.f;
        for (int k = 0; k < H_D; k++) s += g_wtiT[(size_t)k * TI_M + m] * b_i[4 * H_D + k];
        g_vc[m] = s;
    }
}

__global__ void k_init(const float* __restrict__ c0)
{
    int i = blockIdx.x * 256 + threadIdx.x;
    if (i < HB) g_c[i] = c0[i];
    if (i == 0) g_barcnt = 0u;
}

// ------------------------------ phase A ------------------------------------
__global__ void __launch_bounds__(256, 2)
k_x(const float* __restrict__ inputs, const float* __restrict__ lms,
    const float* __restrict__ poses, const float* __restrict__ caps,
    const float* __restrict__ w_lmw, const float* __restrict__ w_posw,
    const float* __restrict__ w_capw)
{
    __shared__ float sm[2 * 16 * 128];
    int t = blockIdx.z, m0 = blockIdx.y * 128, n0 = blockIdx.x * 128;
    float acc[8][8] = {};
    gk128(w_lmw,  lms   + (size_t)t * LM_D  * B_D, LM_D,  IN_D, B_D, m0, n0, acc, sm);
    gk128(w_posw, poses + (size_t)t * POS_D * B_D, POS_D, IN_D, B_D, m0, n0, acc, sm);
    gk128(w_capw, caps  + (size_t)t * CAP_D * B_D, CAP_D, IN_D, B_D, m0, n0, acc, sm);
    int tx = threadIdx.x % 16, ty = threadIdx.x / 16;
    size_t base = (size_t)t * IN_D * B_D;
#pragma unroll
    for (int i = 0; i < 8; i++) {
        size_t idx = base + (size_t)(m0 + ty * 8 + i) * B_D + n0 + tx * 8;
#pragma unroll
        for (int q = 0; q < 2; q++) {
            float4 v = *(const float4*)&inputs[idx + q * 4];
            *(float4*)&g_x[idx + q * 4] = make_float4(acc[i][q*4] + v.x, acc[i][q*4+1] + v.y,
                                                      acc[i][q*4+2] + v.z, acc[i][q*4+3] + v.w);
        }
    }
}

__global__ void __launch_bounds__(256, 2)
k_tiC(const float* __restrict__ lms, const float* __restrict__ poses,
      const float* __restrict__ caps, const float* __restrict__ t0)
{
    __shared__ float sm[2 * 16 * 128];
    int t = blockIdx.z, m0 = blockIdx.y * 128, n0 = blockIdx.x * 128;
    float acc[8][8] = {};
    if (t == 0) {
        gk128(g_wtiT, t0, H_D, TI_M, B_D, m0, n0, acc, sm);
    } else {
        gk128(g_AlmT,  lms   + (size_t)(t-1) * LM_D  * B_D, LM_D,  TI_M, B_D, m0, n0, acc, sm);
        gk128(g_AposT, poses + (size_t)(t-1) * POS_D * B_D, POS_D, TI_M, B_D, m0, n0, acc, sm);
        gk128(g_AcapT, caps  + (size_t)(t-1) * CAP_D * B_D, CAP_D, TI_M, B_D, m0, n0, acc, sm);
    }
    int tx = threadIdx.x % 16, ty = threadIdx.x / 16;
    size_t base = (size_t)t * TI_M * B_D;
#pragma unroll
    for (int i = 0; i < 8; i++) {
        int m = m0 + ty * 8 + i;
        float vc = (t == 0) ? 0.f : g_vc[m];
        size_t idx = base + (size_t)m * B_D + n0 + tx * 8;
#pragma unroll
        for (int q = 0; q < 2; q++)
            *(float4*)&g_tiC[idx + q * 4] = make_float4(acc[i][q*4] + vc, acc[i][q*4+1] + vc,
                                                        acc[i][q*4+2] + vc, acc[i][q*4+3] + vc);
    }
}

__global__ void __launch_bounds__(256, 2)
k_ii(const float* __restrict__ b_i)
{
    __shared__ float sm[2 * 16 * 128];
    int t = blockIdx.z, m0 = blockIdx.y * 128, n0 = blockIdx.x * 128;
    float acc[8][8] = {};
    gk128(g_wiiT, g_x + (size_t)t * IN_D * B_D, IN_D, GATE_M, B_D, m0, n0, acc, sm);
    int tx = threadIdx.x % 16, ty = threadIdx.x / 16;
    size_t base = (size_t)t * GATE_M * B_D;
    size_t tib  = (size_t)t * TI_M * B_D;
#pragma unroll
    for (int i = 0; i < 8; i++) {
        int m = m0 + ty * 8 + i;
        int g = m & 3, r = m >> 2;
        float bb = b_i[g * H_D + r];
        size_t oidx = base + (size_t)m * B_D + n0 + tx * 8;
#pragma unroll
        for (int q = 0; q < 2; q++) {
            float4 tc = make_float4(0.f, 0.f, 0.f, 0.f);
            if (g < 3) tc = *(const float4*)&g_tiC[tib + (size_t)(g * H_D + r) * B_D + n0 + tx * 8 + q * 4];
            *(float4*)&g_pre[oidx + q * 4] = make_float4(acc[i][q*4] + tc.x + bb, acc[i][q*4+1] + tc.y + bb,
                                                         acc[i][q*4+2] + tc.z + bb, acc[i][q*4+3] + tc.w + bb);
        }
    }
}

// --------------------- persistent serial loop (one kernel) ------------------
__device__ __forceinline__ void grid_bar(unsigned target)
{
    __syncthreads();
    if (threadIdx.x == 0) {
        __threadfence();
        atomicAdd(&g_barcnt, 1u);
        while (*((volatile unsigned*)&g_barcnt) < target) __nanosleep(64);
    }
    __syncthreads();
    __threadfence();   // gpu-scope fence -> CCTL.IVALL: invalidate stale L1 lines
}

__global__ void __launch_bounds__(256)
k_loop(const float* __restrict__ h0)
{
    __shared__ float sm[2048];
    const int cta = blockIdx.x;
    const int tx = threadIdx.x % 16, ty = threadIdx.x / 16;
    unsigned gen = 0;

    for (int t = 0; t < T_STEPS; t++) {
        const float* hprev = (t == 0) ? h0 : (g_hall + (size_t)(t - 1) * HB);
        // ---- phase 1: gates + c update ----
        {
            int m0 = (cta >> 2) * 64, n0 = (cta & 3) * 64;
            float acc[4][4] = {};
            gk<64,64,16,4,4>(g_wfT, hprev, H_D, GATE_M, B_D, m0, n0, acc, sm);
            int r = (m0 + ty * 4) >> 2;
            int col = n0 + tx * 4;
            size_t base = (size_t)t * GATE_M * B_D + (size_t)(m0 + ty * 4) * B_D + col;
            float4 pi = *(const float4*)&g_pre[base];
            float4 pf = *(const float4*)&g_pre[base + B_D];
            float4 pz = *(const float4*)&g_pre[base + 2 * B_D];
            float4 po = *(const float4*)&g_pre[base + 3 * B_D];
            float4 co = *(const float4*)&g_c[r * B_D + col];
            float pia[4] = {pi.x, pi.y, pi.z, pi.w}, pfa[4] = {pf.x, pf.y, pf.z, pf.w};
            float pza[4] = {pz.x, pz.y, pz.z, pz.w}, poa[4] = {po.x, po.y, po.z, po.w};
            float coa[4] = {co.x, co.y, co.z, co.w};
            float cn[4], op[4];
#pragma unroll
            for (int j = 0; j < 4; j++) {
                float ig = sigm(acc[0][j] + pia[j]);
                float fg = sigm(acc[1][j] + pfa[j]);
                float zg = tanhf(acc[2][j] + pza[j]);
                cn[j] = fg * coa[j] + ig * zg;
                op[j] = acc[3][j] + poa[j];
            }
            *(float4*)&g_c[r * B_D + col]    = make_float4(cn[0], cn[1], cn[2], cn[3]);
            *(float4*)&g_opre[r * B_D + col] = make_float4(op[0], op[1], op[2], op[3]);
        }
        grid_bar(++gen * NCTA);
        // ---- phase 2: o gate + h ----
        {
            int m0 = (cta >> 3) * 32, n0 = (cta & 7) * 32;
            float acc[2][2] = {};
            gk<32,32,32,2,2>(g_wcoT, g_c, H_D, H_D, B_D, m0, n0, acc, sm);
            size_t hb = (size_t)t * HB;
#pragma unroll
            for (int i = 0; i < 2; i++)
#pragma unroll
                for (int j = 0; j < 2; j++) {
                    int rb = (m0 + ty * 2 + i) * B_D + n0 + tx * 2 + j;
                    float o = sigm(acc[i][j] + g_opre[rb]);
                    g_hall[hb + rb] = o * tanhf(g_c[rb]);
                }
        }
        grid_bar(++gen * NCTA);
    }
}

// ------------------------------ phase C ------------------------------------
// Ts[t] = w_ht@h[t] + b5 + (w_lmt@lm + w_post@pos + w_capt@cap); writes Ts + (b,t,h) out
__global__ void __launch_bounds__(256, 2)
k_Ts(const float* __restrict__ b_i, const float* __restrict__ lms,
     const float* __restrict__ poses, const float* __restrict__ caps,
     float* __restrict__ out)
{
    __shared__ float sm[2 * 16 * 128];
    int t = blockIdx.z, m0 = blockIdx.y * 128, n0 = blockIdx.x * 128;
    float acc[8][8] = {};
    gk128(g_whtT,   g_hall + (size_t)t * HB,            H_D,   H_D, B_D, m0, n0, acc, sm);
    gk128(g_wlmtT,  lms   + (size_t)t * LM_D  * B_D,    LM_D,  H_D, B_D, m0, n0, acc, sm);
    gk128(g_wpostT, poses + (size_t)t * POS_D * B_D,    POS_D, H_D, B_D, m0, n0, acc, sm);
    gk128(g_wcaptT, caps  + (size_t)t * CAP_D * B_D,    CAP_D, H_D, B_D, m0, n0, acc, sm);
    int tx = threadIdx.x % 16, ty = threadIdx.x / 16;
    size_t base = (size_t)t * HB;
    float v[8][8];
#pragma unroll
    for (int i = 0; i < 8; i++) {
        int h = m0 + ty * 8 + i;
        float bb = b_i[4 * H_D + h];
#pragma unroll
        for (int j = 0; j < 8; j++) v[i][j] = acc[i][j] + bb;
        size_t idx = base + (size_t)h * B_D + n0 + tx * 8;
        *(float4*)&g_Ts[idx]     = make_float4(v[i][0], v[i][1], v[i][2], v[i][3]);
        *(float4*)&g_Ts[idx + 4] = make_float4(v[i][4], v[i][5], v[i][6], v[i][7]);
    }
#pragma unroll
    for (int j = 0; j < 8; j++) {
        int b = n0 + tx * 8 + j;
        size_t o = OFF_TS + ((size_t)b * T_STEPS + t) * H_D + m0 + ty * 8;
        *(float4*)&out[o]     = make_float4(v[0][j], v[1][j], v[2][j], v[3][j]);
        *(float4*)&out[o + 4] = make_float4(v[4][j], v[5][j], v[6][j], v[7][j]);
    }
}

__global__ void __launch_bounds__(256)
k_y(const float* __restrict__ byf, const float* __restrict__ byc, float* __restrict__ out)
{
    __shared__ float sm[2 * 64 * 68];
    int t = blockIdx.y, n0 = blockIdx.x * 64;
    const float* Tst = g_Ts + (size_t)t * HB;
    float aF[4][4] = {}, aC[4][4] = {};
    gk<64,64,16,4,4>(g_wyfT, Tst, H_D, TAG, B_D, 0, n0, aF, sm);
    gk<64,64,16,4,4>(g_wycT, Tst, H_D, TAG, B_D, 0, n0, aC, sm);
    float (*yF)[68] = (float (*)[68])sm;
    float (*yC)[68] = (float (*)[68])(sm + 64 * 68);
    int tx = threadIdx.x % 16, ty = threadIdx.x / 16;
#pragma unroll
    for (int i = 0; i < 4; i++)
#pragma unroll
        for (int j = 0; j < 4; j++) {
            int m = ty * 4 + i, n = tx * 4 + j;
            yF[m][n] = aF[i][j] + byf[m];
            yC[m][n] = aC[i][j] + byc[m];
        }
    __syncthreads();
    if (threadIdx.x < 64) {
        int col = threadIdx.x, b = n0 + col;
        float mxF = -1e30f, mxC = -1e30f;
#pragma unroll
        for (int m = 0; m < TAG; m++) {
            mxF = fmaxf(mxF, yF[m][col]);
            mxC = fmaxf(mxC, yC[m][col]);
        }
        float sF = 0.f, sC = 0.f;
#pragma unroll
        for (int m = 0; m < TAG; m++) {
            sF += expf(yF[m][col] - mxF);
            sC += expf(yC[m][col] - mxC);
        }
        float lseF = mxF + logf(sF), lseC = mxC + logf(sC);
        size_t base = ((size_t)b * T_STEPS + t) * TAG;
#pragma unroll
        for (int m = 0; m < TAG; m++) {
            float vf = yF[m][col], vc = yC[m][col];
            out[OFF_LF + base + m] = vf - lseF;
            out[OFF_LC + base + m] = vc - lseC;
            out[OFF_YF + base + m] = vf;
            out[OFF_YC + base + m] = vc;
        }
    }
}

// ------------------------------- launch ------------------------------------
extern "C" void kernel_launch(void* const* d_in, const int* in_sizes, int n_in,
                              void* d_out, int out_size)
{
    const float* inputs   = (const float*)d_in[0];
    const float* lms      = (const float*)d_in[1];
    const float* poses    = (const float*)d_in[2];
    const float* caps     = (const float*)d_in[3];
    const float* h0       = (const float*)d_in[4];
    const float* c0       = (const float*)d_in[5];
    const float* t0       = (const float*)d_in[6];
    const float* w_ii     = (const float*)d_in[7];
    const float* w_hi     = (const float*)d_in[8];
    const float* w_ti     = (const float*)d_in[9];
    const float* w_co     = (const float*)d_in[10];
    const float* w_ht     = (const float*)d_in[11];
    const float* b_i      = (const float*)d_in[12];
    const float* b_y_fact = (const float*)d_in[14];
    const float* b_y_cond = (const float*)d_in[16];
    const float* w_lmw    = (const float*)d_in[17];
    const float* w_posw   = (const float*)d_in[18];
    const float* w_capw   = (const float*)d_in[19];
    const float* w_lmt    = (const float*)d_in[20];
    const float* w_post   = (const float*)d_in[21];
    const float* w_capt   = (const float*)d_in[22];
    float* out = (float*)d_out;

    float* p;
    dim3 tb(32, 8);
    cudaGetSymbolAddress((void**)&p, g_wtiT);
    k_tr<<<dim3(16, 48), tb>>>(w_ti, p, TI_M, H_D);
    cudaGetSymbolAddress((void**)&p, g_whtT);
    k_tr<<<dim3(16, 16), tb>>>(w_ht, p, H_D, H_D);
    cudaGetSymbolAddress((void**)&p, g_wcoT);
    k_tr<<<dim3(16, 16), tb>>>(w_co, p, H_D, H_D);
    cudaGetSymbolAddress((void**)&p, g_wlmtT);
    k_tr<<<dim3(7, 16), tb>>>(w_lmt, p, H_D, LM_D);
    cudaGetSymbolAddress((void**)&p, g_wpostT);
    k_tr<<<dim3(1, 16), tb>>>(w_post, p, H_D, POS_D);
    cudaGetSymbolAddress((void**)&p, g_wcaptT);
    k_tr<<<dim3(1, 16), tb>>>(w_capt, p, H_D, CAP_D);
    cudaGetSymbolAddress((void**)&p, g_wyfT);
    k_tr<<<dim3(16, 2), tb>>>((const float*)d_in[13], p, TAG, H_D);
    cudaGetSymbolAddress((void**)&p, g_wycT);
    k_tr<<<dim3(16, 2), tb>>>((const float*)d_in[15], p, TAG, H_D);

    k_permii<<<dim3(64, 16), tb>>>(w_ii);
    k_w2    <<<dim3(8, 24), 256>>>(w_hi, w_ht);
    k_fillo <<<1024, 256>>>(w_hi);
    k_small <<<(TI_M * (LM_D + POS_D + CAP_D + 1) + 255) / 256, 256>>>(w_lmt, w_post, w_capt, b_i);
    k_init  <<<HB / 256, 256>>>(c0);

    k_x   <<<dim3(2, 4,  T_STEPS), 256>>>(inputs, lms, poses, caps, w_lmw, w_posw, w_capw);
    k_tiC <<<dim3(2, 12, T_STEPS), 256>>>(lms, poses, caps, t0);
    k_ii  <<<dim3(2, 16, T_STEPS), 256>>>(b_i);

    k_loop<<<NCTA, 256>>>(h0);

    k_Ts<<<dim3(2, 4, T_STEPS), 256>>>(b_i, lms, poses, caps, out);
    k_y <<<dim3(4, T_STEPS), 256>>>(b_y_fact, b_y_cond, out);
}

// round 11
// speedup vs baseline: 1.0727x; 1.0727x over previous
#include <cuda_runtime.h>
#include <cuda_bf16.h>
#include <mma.h>
#include <math.h>
#include <stdint.h>

using namespace nvcuda;

#define T_STEPS 128
#define IN_D    512
#define H_D     512
#define B_D     256
#define TAG     64
#define LM_D    200
#define POS_D   6
#define CAP_D   3
#define HB      (H_D * B_D)
#define GATE_M  (4 * H_D)
#define TI_M    (3 * H_D)
#define NCTA    128

#define SEC_Y   ((size_t)B_D * T_STEPS * TAG)
#define OFF_LF  ((size_t)0)
#define OFF_LC  (SEC_Y)
#define OFF_YF  (2 * SEC_Y)
#define OFF_YC  (3 * SEC_Y)
#define OFF_TS  (4 * SEC_Y)

// ------------------------- scratch (device globals) -------------------------
__device__ float g_pre  [(size_t)T_STEPS * GATE_M * B_D];
__device__ float g_tiC  [(size_t)T_STEPS * TI_M   * B_D];
__device__ float g_hall [(size_t)T_STEPS * H_D    * B_D];
__device__ float g_Ts   [(size_t)T_STEPS * H_D    * B_D];
__device__ float g_c    [HB];
__device__ float g_opre [HB];
__device__ unsigned g_barcnt;
// bf16 split operands for tensor k_ii
__device__ __nv_bfloat16 g_wiih[(size_t)GATE_M * IN_D];   // permuted rows [p][k]
__device__ __nv_bfloat16 g_wiil[(size_t)GATE_M * IN_D];
__device__ __nv_bfloat16 g_xTh [(size_t)T_STEPS * B_D * IN_D];  // x^T [t][b][i]
__device__ __nv_bfloat16 g_xTl [(size_t)T_STEPS * B_D * IN_D];
// k-major fp32 weights
__device__ float g_wfT  [(size_t)H_D * GATE_M];
__device__ float g_wtiT [(size_t)H_D * TI_M];
__device__ float g_whtT [(size_t)H_D * H_D];
__device__ float g_wcoT [(size_t)H_D * H_D];
__device__ float g_wlmtT[(size_t)LM_D * H_D];
__device__ float g_wpostT[(size_t)POS_D * H_D];
__device__ float g_wcaptT[(size_t)CAP_D * H_D];
__device__ float g_wyfT [(size_t)H_D * TAG];
__device__ float g_wycT [(size_t)H_D * TAG];
__device__ float g_AlmT [(size_t)LM_D * TI_M];
__device__ float g_AposT[(size_t)POS_D * TI_M];
__device__ float g_AcapT[(size_t)CAP_D * TI_M];
__device__ float g_vc   [TI_M];

__device__ __forceinline__ float sigm(float x) { return 1.f / (1.f + expf(-x)); }
__device__ __forceinline__ void bsplit(float v, __nv_bfloat16& h, __nv_bfloat16& l)
{
    h = __float2bfloat16_rn(v);
    l = __float2bfloat16_rn(v - __bfloat162float(h));
}

// ---------------------------------------------------------------------------
// SIMT GEMM cores (unchanged)
// ---------------------------------------------------------------------------
template <int BM, int BN, int BK, int TM, int TN>
__device__ __forceinline__ void gk(const float* __restrict__ A, const float* __restrict__ B,
                                   int K, int ldA, int ldB, int m0, int n0,
                                   float (&acc)[TM][TN], float* sm)
{
    float (*As)[BM] = (float (*)[BM])sm;
    float (*Bs)[BN] = (float (*)[BN])(sm + BK * BM);
    const int tid = threadIdx.x;
    const int tx = tid % (BN / TN), ty = tid / (BN / TN);
    constexpr int AV = BM / 4, BV = BN / 4;
    constexpr int AL = (BM * BK / 4) / 256, BL = (BN * BK / 4) / 256;
    const float4 z4 = make_float4(0.f, 0.f, 0.f, 0.f);
    for (int k0 = 0; k0 < K; k0 += BK) {
#pragma unroll
        for (int i = 0; i < AL; i++) {
            int li = tid + i * 256, k = li / AV, m4 = (li % AV) * 4;
            float4 v = (k0 + k < K) ? *(const float4*)&A[(size_t)(k0 + k) * ldA + m0 + m4] : z4;
            *(float4*)&As[k][m4] = v;
        }
#pragma unroll
        for (int i = 0; i < BL; i++) {
            int li = tid + i * 256, k = li / BV, n4 = (li % BV) * 4;
            float4 v = (k0 + k < K) ? *(const float4*)&B[(size_t)(k0 + k) * ldB + n0 + n4] : z4;
            *(float4*)&Bs[k][n4] = v;
        }
        __syncthreads();
#pragma unroll
        for (int k = 0; k < BK; k++) {
            float a[TM], b[TN];
            if constexpr (TM % 4 == 0) {
#pragma unroll
                for (int i = 0; i < TM; i += 4) {
                    float4 v = *(const float4*)&As[k][ty * TM + i];
                    a[i] = v.x; a[i+1] = v.y; a[i+2] = v.z; a[i+3] = v.w;
                }
            } else {
                float2 v = *(const float2*)&As[k][ty * TM];
                a[0] = v.x; a[1] = v.y;
            }
            if constexpr (TN == 4) {
                float4 v = *(const float4*)&Bs[k][tx * 4];
                b[0] = v.x; b[1] = v.y; b[2] = v.z; b[3] = v.w;
            } else {
                float2 v = *(const float2*)&Bs[k][tx * 2];
                b[0] = v.x; b[1] = v.y;
            }
#pragma unroll
            for (int i = 0; i < TM; i++)
#pragma unroll
                for (int j = 0; j < TN; j++) acc[i][j] += a[i] * b[j];
        }
        __syncthreads();
    }
}

__device__ __forceinline__ void gk128(const float* __restrict__ A, const float* __restrict__ B,
                                      int K, int ldA, int ldB, int m0, int n0,
                                      float (&acc)[8][8], float* sm)
{
    float (*As)[128] = (float (*)[128])sm;
    float (*Bs)[128] = (float (*)[128])(sm + 16 * 128);
    const int tid = threadIdx.x;
    const int tx = tid % 16, ty = tid / 16;
    const float4 z4 = make_float4(0.f, 0.f, 0.f, 0.f);
    for (int k0 = 0; k0 < K; k0 += 16) {
#pragma unroll
        for (int i = 0; i < 2; i++) {
            int li = tid + i * 256, k = li / 32, m4 = (li % 32) * 4;
            float4 va = (k0 + k < K) ? *(const float4*)&A[(size_t)(k0 + k) * ldA + m0 + m4] : z4;
            *(float4*)&As[k][m4] = va;
            float4 vb = (k0 + k < K) ? *(const float4*)&B[(size_t)(k0 + k) * ldB + n0 + m4] : z4;
            *(float4*)&Bs[k][m4] = vb;
        }
        __syncthreads();
#pragma unroll
        for (int k = 0; k < 16; k++) {
            float a[8], b[8];
            float4 v0 = *(const float4*)&As[k][ty * 8];
            float4 v1 = *(const float4*)&As[k][ty * 8 + 4];
            a[0]=v0.x; a[1]=v0.y; a[2]=v0.z; a[3]=v0.w; a[4]=v1.x; a[5]=v1.y; a[6]=v1.z; a[7]=v1.w;
            float4 w0 = *(const float4*)&Bs[k][tx * 8];
            float4 w1 = *(const float4*)&Bs[k][tx * 8 + 4];
            b[0]=w0.x; b[1]=w0.y; b[2]=w0.z; b[3]=w0.w; b[4]=w1.x; b[5]=w1.y; b[6]=w1.z; b[7]=w1.w;
#pragma unroll
            for (int i = 0; i < 8; i++)
#pragma unroll
                for (int j = 0; j < 8; j++) acc[i][j] += a[i] * b[j];
        }
        __syncthreads();
    }
}

// --------------------------- one-time precompute ---------------------------
__global__ void k_tr(const float* __restrict__ in, float* __restrict__ out, int M, int K)
{
    __shared__ float tl[32][33];
    int k0 = blockIdx.x * 32, m0 = blockIdx.y * 32;
    int tx = threadIdx.x, ty = threadIdx.y;
    for (int i = ty; i < 32; i += 8)
        if (m0 + i < M && k0 + tx < K) tl[i][tx] = in[(size_t)(m0 + i) * K + k0 + tx];
    __syncthreads();
    for (int i = ty; i < 32; i += 8)
        if (k0 + i < K && m0 + tx < M) out[(size_t)(k0 + i) * M + m0 + tx] = tl[tx][i];
}

__global__ void k_permii(const float* __restrict__ w_ii)
{
    int idx = blockIdx.x * 256 + threadIdx.x;
    if (idx >= GATE_M * IN_D) return;
    int p = idx >> 9, k = idx & 511;
    int m = (p & 3) * H_D + (p >> 2);
    __nv_bfloat16 h, l;
    bsplit(w_ii[(size_t)m * IN_D + k], h, l);
    g_wiih[idx] = h; g_wiil[idx] = l;
}

__global__ void __launch_bounds__(256)
k_w2(const float* __restrict__ w_hi, const float* __restrict__ w_ht)
{
    __shared__ float sm[16 * 128];
    int n0 = blockIdx.x * 64, m0 = blockIdx.y * 64;
    float acc[4][4] = {};
    gk<64,64,16,4,4>(g_wtiT, w_ht, H_D, TI_M, H_D, m0, n0, acc, sm);
    int tx = threadIdx.x % 16, ty = threadIdx.x / 16;
#pragma unroll
    for (int i = 0; i < 4; i++) {
        int m = m0 + ty * 4 + i;
        int p = (m & 511) * 4 + (m >> 9);
#pragma unroll
        for (int j = 0; j < 4; j++) {
            int jc = n0 + tx * 4 + j;
            g_wfT[(size_t)jc * GATE_M + p] = acc[i][j] + w_hi[(size_t)m * H_D + jc];
        }
    }
}

__global__ void k_fillo(const float* __restrict__ w_hi)
{
    int idx = blockIdx.x * 256 + threadIdx.x;
    if (idx >= H_D * H_D) return;
    int r = idx >> 9, j = idx & 511;
    g_wfT[(size_t)j * GATE_M + 4 * r + 3] = w_hi[(size_t)(3 * H_D + r) * H_D + j];
}

__global__ void k_small(const float* __restrict__ w_lmt, const float* __restrict__ w_post,
                        const float* __restrict__ w_capt, const float* __restrict__ b_i)
{
    int idx = blockIdx.x * 256 + threadIdx.x;
    if (idx < TI_M * LM_D) {
        int l = idx / TI_M, m = idx % TI_M;
        float s = 0.f;
        for (int k = 0; k < H_D; k++) s += g_wtiT[(size_t)k * TI_M + m] * w_lmt[k * LM_D + l];
        g_AlmT[(size_t)l * TI_M + m] = s;
    } else if (idx < TI_M * (LM_D + POS_D)) {
        int q = idx - TI_M * LM_D, l = q / TI_M, m = q % TI_M;
        float s = 0.f;
        for (int k = 0; k < H_D; k++) s += g_wtiT[(size_t)k * TI_M + m] * w_post[k * POS_D + l];
        g_AposT[(size_t)l * TI_M + m] = s;
    } else if (idx < TI_M * (LM_D + POS_D + CAP_D)) {
        int q = idx - TI_M * (LM_D + POS_D), l = q / TI_M, m = q % TI_M;
        float s = 0.f;
        for (int k = 0; k < H_D; k++) s += g_wtiT[(size_t)k * TI_M + m] * w_capt[k * CAP_D + l];
        g_AcapT[(size_t)l * TI_M + m] = s;
    } else if (idx < TI_M * (LM_D + POS_D + CAP_D + 1)) {
        int m = idx - TI_M * (LM_D + POS_D + CAP_D);
        float s = 0.f;
        for (int k = 0; k < H_D; k++) s += g_wtiT[(size_t)k * TI_M + m] * b_i[4 * H_D + k];
        g_vc[m] = s;
    }
}

__global__ void k_init(const float* __restrict__ c0)
{
    int i = blockIdx.x * 256 + threadIdx.x;
    if (i < HB) g_c[i] = c0[i];
    if (i == 0) g_barcnt = 0u;
}

// ------------------------------ phase A ------------------------------------
// x = inputs + emb projections; emitted directly as bf16-split x^T [t][b][i]
__global__ void __launch_bounds__(256, 2)
k_x(const float* __restrict__ inputs, const float* __restrict__ lms,
    const float* __restrict__ poses, const float* __restrict__ caps,
    const float* __restrict__ w_lmw, const float* __restrict__ w_posw,
    const float* __restrict__ w_capw)
{
    __shared__ float sm[2 * 16 * 128];
    int t = blockIdx.z, m0 = blockIdx.y * 128, n0 = blockIdx.x * 128;
    float acc[8][8] = {};
    gk128(w_lmw,  lms   + (size_t)t * LM_D  * B_D, LM_D,  IN_D, B_D, m0, n0, acc, sm);
    gk128(w_posw, poses + (size_t)t * POS_D * B_D, POS_D, IN_D, B_D, m0, n0, acc, sm);
    gk128(w_capw, caps  + (size_t)t * CAP_D * B_D, CAP_D, IN_D, B_D, m0, n0, acc, sm);
    int tx = threadIdx.x % 16, ty = threadIdx.x / 16;
    size_t base = (size_t)t * IN_D * B_D;
    float xv[8][8];
#pragma unroll
    for (int i = 0; i < 8; i++) {
        size_t idx = base + (size_t)(m0 + ty * 8 + i) * B_D + n0 + tx * 8;
#pragma unroll
        for (int q = 0; q < 2; q++) {
            float4 v = *(const float4*)&inputs[idx + q * 4];
            xv[i][q*4+0] = acc[i][q*4+0] + v.x; xv[i][q*4+1] = acc[i][q*4+1] + v.y;
            xv[i][q*4+2] = acc[i][q*4+2] + v.z; xv[i][q*4+3] = acc[i][q*4+3] + v.w;
        }
    }
#pragma unroll
    for (int j = 0; j < 8; j++) {
        int b = n0 + tx * 8 + j;
        __align__(16) __nv_bfloat16 ah[8], al[8];
#pragma unroll
        for (int i = 0; i < 8; i++) bsplit(xv[i][j], ah[i], al[i]);
        size_t o = ((size_t)t * B_D + b) * IN_D + m0 + ty * 8;
        *(uint4*)&g_xTh[o] = *(uint4*)ah;
        *(uint4*)&g_xTl[o] = *(uint4*)al;
    }
}

__global__ void __launch_bounds__(256, 2)
k_tiC(const float* __restrict__ lms, const float* __restrict__ poses,
      const float* __restrict__ caps, const float* __restrict__ t0)
{
    __shared__ float sm[2 * 16 * 128];
    int t = blockIdx.z, m0 = blockIdx.y * 128, n0 = blockIdx.x * 128;
    float acc[8][8] = {};
    if (t == 0) {
        gk128(g_wtiT, t0, H_D, TI_M, B_D, m0, n0, acc, sm);
    } else {
        gk128(g_AlmT,  lms   + (size_t)(t-1) * LM_D  * B_D, LM_D,  TI_M, B_D, m0, n0, acc, sm);
        gk128(g_AposT, poses + (size_t)(t-1) * POS_D * B_D, POS_D, TI_M, B_D, m0, n0, acc, sm);
        gk128(g_AcapT, caps  + (size_t)(t-1) * CAP_D * B_D, CAP_D, TI_M, B_D, m0, n0, acc, sm);
    }
    int tx = threadIdx.x % 16, ty = threadIdx.x / 16;
    size_t base = (size_t)t * TI_M * B_D;
#pragma unroll
    for (int i = 0; i < 8; i++) {
        int m = m0 + ty * 8 + i;
        float vc = (t == 0) ? 0.f : g_vc[m];
        size_t idx = base + (size_t)m * B_D + n0 + tx * 8;
#pragma unroll
        for (int q = 0; q < 2; q++)
            *(float4*)&g_tiC[idx + q * 4] = make_float4(acc[i][q*4] + vc, acc[i][q*4+1] + vc,
                                                        acc[i][q*4+2] + vc, acc[i][q*4+3] + vc);
    }
}

// -------- wmma (HMMA) k_ii: g_pre = w_ii@x + tiC + b, 3-product bf16 --------
// CTA: 128 (p rows) x 128 (b cols); 8 warps of 64x32; K chunk 32.
#define LDS_K 40
__global__ void __launch_bounds__(256)
k_ii_wm(const float* __restrict__ b_i)
{
    extern __shared__ char dsm[];
    __nv_bfloat16 (*Ah)[LDS_K] = (__nv_bfloat16 (*)[LDS_K])(dsm);
    __nv_bfloat16 (*Al)[LDS_K] = (__nv_bfloat16 (*)[LDS_K])(dsm + 10240);
    __nv_bfloat16 (*Bh)[LDS_K] = (__nv_bfloat16 (*)[LDS_K])(dsm + 20480);
    __nv_bfloat16 (*Bl)[LDS_K] = (__nv_bfloat16 (*)[LDS_K])(dsm + 30720);

    const int t = blockIdx.z, m0 = blockIdx.x * 128, n0 = blockIdx.y * 128;
    const int tid = threadIdx.x, wid = tid / 32, lane = tid % 32;
    const int wr = wid >> 2, wc = wid & 3;            // 2x4 warp grid

    wmma::fragment<wmma::accumulator, 16, 16, 16, float> acc[4][2];
#pragma unroll
    for (int i = 0; i < 4; i++)
#pragma unroll
        for (int j = 0; j < 2; j++) wmma::fill_fragment(acc[i][j], 0.f);

    const __nv_bfloat16* wh = g_wiih + (size_t)m0 * IN_D;
    const __nv_bfloat16* wl = g_wiil + (size_t)m0 * IN_D;
    const __nv_bfloat16* xh = g_xTh + ((size_t)t * B_D + n0) * IN_D;
    const __nv_bfloat16* xl = g_xTl + ((size_t)t * B_D + n0) * IN_D;

    for (int ch = 0; ch < 16; ch++) {
        // fill 128x32 tiles (A hi/lo from w, B hi/lo from x^T), uint4 = 8 bf16
#pragma unroll
        for (int it = 0; it < 2; it++) {
            int s = tid + it * 256, r = s >> 2, kq = (s & 3) * 8;
            *(uint4*)&Ah[r][kq] = *(const uint4*)(wh + (size_t)r * IN_D + ch * 32 + kq);
            *(uint4*)&Al[r][kq] = *(const uint4*)(wl + (size_t)r * IN_D + ch * 32 + kq);
            *(uint4*)&Bh[r][kq] = *(const uint4*)(xh + (size_t)r * IN_D + ch * 32 + kq);
            *(uint4*)&Bl[r][kq] = *(const uint4*)(xl + (size_t)r * IN_D + ch * 32 + kq);
        }
        __syncthreads();
#pragma unroll
        for (int kk = 0; kk < 2; kk++) {
            wmma::fragment<wmma::matrix_b, 16, 16, 16, __nv_bfloat16, wmma::col_major> bh[2], bl[2];
#pragma unroll
            for (int j = 0; j < 2; j++) {
                wmma::load_matrix_sync(bh[j], &Bh[wc * 32 + j * 16][kk * 16], LDS_K);
                wmma::load_matrix_sync(bl[j], &Bl[wc * 32 + j * 16][kk * 16], LDS_K);
            }
#pragma unroll
            for (int i = 0; i < 4; i++) {
                wmma::fragment<wmma::matrix_a, 16, 16, 16, __nv_bfloat16, wmma::row_major> ah, al;
                wmma::load_matrix_sync(ah, &Ah[wr * 64 + i * 16][kk * 16], LDS_K);
                wmma::load_matrix_sync(al, &Al[wr * 64 + i * 16][kk * 16], LDS_K);
#pragma unroll
                for (int j = 0; j < 2; j++) {
                    wmma::mma_sync(acc[i][j], ah, bh[j], acc[i][j]);
                    wmma::mma_sync(acc[i][j], ah, bl[j], acc[i][j]);
                    wmma::mma_sync(acc[i][j], al, bh[j], acc[i][j]);
                }
            }
        }
        __syncthreads();
    }

    // epilogue: per-warp 16x16 staging (ld=20 fp32), fold tiC + bias
    float (*eb)[20] = (float (*)[20])(dsm + wid * 1280);
    size_t preb = (size_t)t * GATE_M * B_D;
    size_t tib  = (size_t)t * TI_M * B_D;
#pragma unroll 1
    for (int i = 0; i < 4; i++)
#pragma unroll 1
        for (int j = 0; j < 2; j++) {
            wmma::store_matrix_sync(&eb[0][0], acc[i][j], 20, wmma::mem_row_major);
            __syncwarp();
            int r0 = lane >> 1, c0 = (lane & 1) * 8;
            int p = m0 + wr * 64 + i * 16 + r0;
            int b = n0 + wc * 32 + j * 16 + c0;
            int g = p & 3, rr = p >> 2;
            float add = b_i[g * H_D + rr];
            float v[8];
#pragma unroll
            for (int q = 0; q < 8; q++) v[q] = eb[r0][c0 + q] + add;
            if (g < 3) {
                const float* tc = &g_tiC[tib + (size_t)(g * H_D + rr) * B_D + b];
#pragma unroll
                for (int q = 0; q < 8; q++) v[q] += tc[q];
            }
            float* dst = &g_pre[preb + (size_t)p * B_D + b];
            *(float4*)dst       = make_float4(v[0], v[1], v[2], v[3]);
            *(float4*)(dst + 4) = make_float4(v[4], v[5], v[6], v[7]);
            __syncwarp();
        }
}

// --------------------- persistent serial loop (unchanged) -------------------
__device__ __forceinline__ void grid_bar(unsigned target)
{
    __syncthreads();
    if (threadIdx.x == 0) {
        __threadfence();
        atomicAdd(&g_barcnt, 1u);
        while (*((volatile unsigned*)&g_barcnt) < target) __nanosleep(64);
    }
    __syncthreads();
    __threadfence();
}

__global__ void __launch_bounds__(256)
k_loop(const float* __restrict__ h0)
{
    __shared__ float sm[2048];
    const int cta = blockIdx.x;
    const int tx = threadIdx.x % 16, ty = threadIdx.x / 16;
    unsigned gen = 0;

    for (int t = 0; t < T_STEPS; t++) {
        const float* hprev = (t == 0) ? h0 : (g_hall + (size_t)(t - 1) * HB);
        {
            int m0 = (cta >> 2) * 64, n0 = (cta & 3) * 64;
            float acc[4][4] = {};
            gk<64,64,16,4,4>(g_wfT, hprev, H_D, GATE_M, B_D, m0, n0, acc, sm);
            int r = (m0 + ty * 4) >> 2;
            int col = n0 + tx * 4;
            size_t base = (size_t)t * GATE_M * B_D + (size_t)(m0 + ty * 4) * B_D + col;
            float4 pi = *(const float4*)&g_pre[base];
            float4 pf = *(const float4*)&g_pre[base + B_D];
            float4 pz = *(const float4*)&g_pre[base + 2 * B_D];
            float4 po = *(const float4*)&g_pre[base + 3 * B_D];
            float4 co = *(const float4*)&g_c[r * B_D + col];
            float pia[4] = {pi.x, pi.y, pi.z, pi.w}, pfa[4] = {pf.x, pf.y, pf.z, pf.w};
            float pza[4] = {pz.x, pz.y, pz.z, pz.w}, poa[4] = {po.x, po.y, po.z, po.w};
            float coa[4] = {co.x, co.y, co.z, co.w};
            float cn[4], op[4];
#pragma unroll
            for (int j = 0; j < 4; j++) {
                float ig = sigm(acc[0][j] + pia[j]);
                float fg = sigm(acc[1][j] + pfa[j]);
                float zg = tanhf(acc[2][j] + pza[j]);
                cn[j] = fg * coa[j] + ig * zg;
                op[j] = acc[3][j] + poa[j];
            }
            *(float4*)&g_c[r * B_D + col]    = make_float4(cn[0], cn[1], cn[2], cn[3]);
            *(float4*)&g_opre[r * B_D + col] = make_float4(op[0], op[1], op[2], op[3]);
        }
        grid_bar(++gen * NCTA);
        {
            int m0 = (cta >> 3) * 32, n0 = (cta & 7) * 32;
            float acc[2][2] = {};
            gk<32,32,32,2,2>(g_wcoT, g_c, H_D, H_D, B_D, m0, n0, acc, sm);
            size_t hb = (size_t)t * HB;
#pragma unroll
            for (int i = 0; i < 2; i++)
#pragma unroll
                for (int j = 0; j < 2; j++) {
                    int rb = (m0 + ty * 2 + i) * B_D + n0 + tx * 2 + j;
                    float o = sigm(acc[i][j] + g_opre[rb]);
                    g_hall[hb + rb] = o * tanhf(g_c[rb]);
                }
        }
        grid_bar(++gen * NCTA);
    }
}

// ------------------------------ phase C (unchanged) -------------------------
__global__ void __launch_bounds__(256, 2)
k_Ts(const float* __restrict__ b_i, const float* __restrict__ lms,
     const float* __restrict__ poses, const float* __restrict__ caps,
     float* __restrict__ out)
{
    __shared__ float sm[2 * 16 * 128];
    int t = blockIdx.z, m0 = blockIdx.y * 128, n0 = blockIdx.x * 128;
    float acc[8][8] = {};
    gk128(g_whtT,   g_hall + (size_t)t * HB,         H_D,   H_D, B_D, m0, n0, acc, sm);
    gk128(g_wlmtT,  lms   + (size_t)t * LM_D  * B_D, LM_D,  H_D, B_D, m0, n0, acc, sm);
    gk128(g_wpostT, poses + (size_t)t * POS_D * B_D, POS_D, H_D, B_D, m0, n0, acc, sm);
    gk128(g_wcaptT, caps  + (size_t)t * CAP_D * B_D, CAP_D, H_D, B_D, m0, n0, acc, sm);
    int tx = threadIdx.x % 16, ty = threadIdx.x / 16;
    size_t base = (size_t)t * HB;
    float v[8][8];
#pragma unroll
    for (int i = 0; i < 8; i++) {
        int h = m0 + ty * 8 + i;
        float bb = b_i[4 * H_D + h];
#pragma unroll
        for (int j = 0; j < 8; j++) v[i][j] = acc[i][j] + bb;
        size_t idx = base + (size_t)h * B_D + n0 + tx * 8;
        *(float4*)&g_Ts[idx]     = make_float4(v[i][0], v[i][1], v[i][2], v[i][3]);
        *(float4*)&g_Ts[idx + 4] = make_float4(v[i][4], v[i][5], v[i][6], v[i][7]);
    }
#pragma unroll
    for (int j = 0; j < 8; j++) {
        int b = n0 + tx * 8 + j;
        size_t o = OFF_TS + ((size_t)b * T_STEPS + t) * H_D + m0 + ty * 8;
        *(float4*)&out[o]     = make_float4(v[0][j], v[1][j], v[2][j], v[3][j]);
        *(float4*)&out[o + 4] = make_float4(v[4][j], v[5][j], v[6][j], v[7][j]);
    }
}

__global__ void __launch_bounds__(256)
k_y(const float* __restrict__ byf, const float* __restrict__ byc, float* __restrict__ out)
{
    __shared__ float sm[2 * 64 * 68];
    int t = blockIdx.y, n0 = blockIdx.x * 64;
    const float* Tst = g_Ts + (size_t)t * HB;
    float aF[4][4] = {}, aC[4][4] = {};
    gk<64,64,16,4,4>(g_wyfT, Tst, H_D, TAG, B_D, 0, n0, aF, sm);
    gk<64,64,16,4,4>(g_wycT, Tst, H_D, TAG, B_D, 0, n0, aC, sm);
    float (*yF)[68] = (float (*)[68])sm;
    float (*yC)[68] = (float (*)[68])(sm + 64 * 68);
    int tx = threadIdx.x % 16, ty = threadIdx.x / 16;
#pragma unroll
    for (int i = 0; i < 4; i++)
#pragma unroll
        for (int j = 0; j < 4; j++) {
            int m = ty * 4 + i, n = tx * 4 + j;
            yF[m][n] = aF[i][j] + byf[m];
            yC[m][n] = aC[i][j] + byc[m];
        }
    __syncthreads();
    if (threadIdx.x < 64) {
        int col = threadIdx.x, b = n0 + col;
        float mxF = -1e30f, mxC = -1e30f;
#pragma unroll
        for (int m = 0; m < TAG; m++) {
            mxF = fmaxf(mxF, yF[m][col]);
            mxC = fmaxf(mxC, yC[m][col]);
        }
        float sF = 0.f, sC = 0.f;
#pragma unroll
        for (int m = 0; m < TAG; m++) {
            sF += expf(yF[m][col] - mxF);
            sC += expf(yC[m][col] - mxC);
        }
        float lseF = mxF + logf(sF), lseC = mxC + logf(sC);
        size_t base = ((size_t)b * T_STEPS + t) * TAG;
#pragma unroll
        for (int m = 0; m < TAG; m++) {
            float vf = yF[m][col], vc = yC[m][col];
            out[OFF_LF + base + m] = vf - lseF;
            out[OFF_LC + base + m] = vc - lseC;
            out[OFF_YF + base + m] = vf;
            out[OFF_YC + base + m] = vc;
        }
    }
}

// ------------------------------- launch ------------------------------------
extern "C" void kernel_launch(void* const* d_in, const int* in_sizes, int n_in,
                              void* d_out, int out_size)
{
    const float* inputs   = (const float*)d_in[0];
    const float* lms      = (const float*)d_in[1];
    const float* poses    = (const float*)d_in[2];
    const float* caps     = (const float*)d_in[3];
    const float* h0       = (const float*)d_in[4];
    const float* c0       = (const float*)d_in[5];
    const float* t0       = (const float*)d_in[6];
    const float* w_ii     = (const float*)d_in[7];
    const float* w_hi     = (const float*)d_in[8];
    const float* w_ti     = (const float*)d_in[9];
    const float* w_co     = (const float*)d_in[10];
    const float* w_ht     = (const float*)d_in[11];
    const float* b_i      = (const float*)d_in[12];
    const float* b_y_fact = (const float*)d_in[14];
    const float* b_y_cond = (const float*)d_in[16];
    const float* w_lmw    = (const float*)d_in[17];
    const float* w_posw   = (const float*)d_in[18];
    const float* w_capw   = (const float*)d_in[19];
    const float* w_lmt    = (const float*)d_in[20];
    const float* w_post   = (const float*)d_in[21];
    const float* w_capt   = (const float*)d_in[22];
    float* out = (float*)d_out;

    float* p;
    dim3 tb(32, 8);
    cudaGetSymbolAddress((void**)&p, g_wtiT);
    k_tr<<<dim3(16, 48), tb>>>(w_ti, p, TI_M, H_D);
    cudaGetSymbolAddress((void**)&p, g_whtT);
    k_tr<<<dim3(16, 16), tb>>>(w_ht, p, H_D, H_D);
    cudaGetSymbolAddress((void**)&p, g_wcoT);
    k_tr<<<dim3(16, 16), tb>>>(w_co, p, H_D, H_D);
    cudaGetSymbolAddress((void**)&p, g_wlmtT);
    k_tr<<<dim3(7, 16), tb>>>(w_lmt, p, H_D, LM_D);
    cudaGetSymbolAddress((void**)&p, g_wpostT);
    k_tr<<<dim3(1, 16), tb>>>(w_post, p, H_D, POS_D);
    cudaGetSymbolAddress((void**)&p, g_wcaptT);
    k_tr<<<dim3(1, 16), tb>>>(w_capt, p, H_D, CAP_D);
    cudaGetSymbolAddress((void**)&p, g_wyfT);
    k_tr<<<dim3(16, 2), tb>>>((const float*)d_in[13], p, TAG, H_D);
    cudaGetSymbolAddress((void**)&p, g_wycT);
    k_tr<<<dim3(16, 2), tb>>>((const float*)d_in[15], p, TAG, H_D);

    k_permii<<<(GATE_M * IN_D) / 256, 256>>>(w_ii);
    k_w2    <<<dim3(8, 24), 256>>>(w_hi, w_ht);
    k_fillo <<<1024, 256>>>(w_hi);
    k_small <<<(TI_M * (LM_D + POS_D + CAP_D + 1) + 255) / 256, 256>>>(w_lmt, w_post, w_capt, b_i);
    k_init  <<<HB / 256, 256>>>(c0);

    k_x    <<<dim3(2, 4,  T_STEPS), 256>>>(inputs, lms, poses, caps, w_lmw, w_posw, w_capw);
    k_tiC  <<<dim3(2, 12, T_STEPS), 256>>>(lms, poses, caps, t0);
    k_ii_wm<<<dim3(16, 2, T_STEPS), 256, 40960>>>(b_i);

    k_loop<<<NCTA, 256>>>(h0);

    k_Ts<<<dim3(2, 4, T_STEPS), 256>>>(b_i, lms, poses, caps, out);
    k_y <<<dim3(4, T_STEPS), 256>>>(b_y_fact, b_y_cond, out);
}

// round 12
// speedup vs baseline: 1.0951x; 1.0208x over previous
#include <cuda_runtime.h>
#include <cuda_bf16.h>
#include <mma.h>
#include <math.h>
#include <stdint.h>

using namespace nvcuda;

#define T_STEPS 128
#define IN_D    512
#define H_D     512
#define B_D     256
#define TAG     64
#define LM_D    200
#define POS_D   6
#define CAP_D   3
#define HB      (H_D * B_D)
#define GATE_M  (4 * H_D)
#define TI_M    (3 * H_D)
#define NCTA    128
#define KE      224          // padded emb K (200+6+3 -> 224)
#define KT      736          // 512 (h) + 224 (emb)

#define SEC_Y   ((size_t)B_D * T_STEPS * TAG)
#define OFF_LF  ((size_t)0)
#define OFF_LC  (SEC_Y)
#define OFF_YF  (2 * SEC_Y)
#define OFF_YC  (3 * SEC_Y)
#define OFF_TS  (4 * SEC_Y)

// ------------------------- scratch (device globals) -------------------------
__device__ float g_pre  [(size_t)T_STEPS * GATE_M * B_D];
__device__ float g_tiC  [(size_t)T_STEPS * TI_M   * B_D];
__device__ float g_hall [(size_t)T_STEPS * H_D    * B_D];
__device__ float g_Ts   [(size_t)T_STEPS * H_D    * B_D];
__device__ float g_c    [HB];
__device__ float g_opre [HB];
__device__ unsigned g_barcnt;
// bf16 split operands
__device__ __nv_bfloat16 g_wiih[(size_t)GATE_M * IN_D];
__device__ __nv_bfloat16 g_wiil[(size_t)GATE_M * IN_D];
__device__ __nv_bfloat16 g_xTh [(size_t)T_STEPS * B_D * IN_D];
__device__ __nv_bfloat16 g_xTl [(size_t)T_STEPS * B_D * IN_D];
__device__ __nv_bfloat16 g_bTh [(size_t)T_STEPS * B_D * KT];   // [t][b][ h(512) | emb(224) ]
__device__ __nv_bfloat16 g_bTl [(size_t)T_STEPS * B_D * KT];
__device__ __nv_bfloat16 g_AtsH[(size_t)H_D * KT];   // [w_ht | w_lmt | w_post | w_capt]
__device__ __nv_bfloat16 g_AtsL[(size_t)H_D * KT];
__device__ __nv_bfloat16 g_AtcH[(size_t)TI_M * KE];  // [A_lm | A_pos | A_cap]
__device__ __nv_bfloat16 g_AtcL[(size_t)TI_M * KE];
// fp32 k-major weights still used
__device__ float g_wfT  [(size_t)H_D * GATE_M];
__device__ float g_wtiT [(size_t)H_D * TI_M];
__device__ float g_wcoT [(size_t)H_D * H_D];
__device__ float g_wyfT [(size_t)H_D * TAG];
__device__ float g_wycT [(size_t)H_D * TAG];
__device__ float g_vc   [TI_M];

__device__ __forceinline__ float sigm(float x) { return 1.f / (1.f + expf(-x)); }
__device__ __forceinline__ void bsplit(float v, __nv_bfloat16& h, __nv_bfloat16& l)
{
    h = __float2bfloat16_rn(v);
    l = __float2bfloat16_rn(v - __bfloat162float(h));
}

// ---------------------------------------------------------------------------
// SIMT GEMM cores
// ---------------------------------------------------------------------------
template <int BM, int BN, int BK, int TM, int TN>
__device__ __forceinline__ void gk(const float* __restrict__ A, const float* __restrict__ B,
                                   int K, int ldA, int ldB, int m0, int n0,
                                   float (&acc)[TM][TN], float* sm)
{
    float (*As)[BM] = (float (*)[BM])sm;
    float (*Bs)[BN] = (float (*)[BN])(sm + BK * BM);
    const int tid = threadIdx.x;
    const int tx = tid % (BN / TN), ty = tid / (BN / TN);
    constexpr int AV = BM / 4, BV = BN / 4;
    constexpr int AL = (BM * BK / 4) / 256, BL = (BN * BK / 4) / 256;
    const float4 z4 = make_float4(0.f, 0.f, 0.f, 0.f);
    for (int k0 = 0; k0 < K; k0 += BK) {
#pragma unroll
        for (int i = 0; i < AL; i++) {
            int li = tid + i * 256, k = li / AV, m4 = (li % AV) * 4;
            float4 v = (k0 + k < K) ? *(const float4*)&A[(size_t)(k0 + k) * ldA + m0 + m4] : z4;
            *(float4*)&As[k][m4] = v;
        }
#pragma unroll
        for (int i = 0; i < BL; i++) {
            int li = tid + i * 256, k = li / BV, n4 = (li % BV) * 4;
            float4 v = (k0 + k < K) ? *(const float4*)&B[(size_t)(k0 + k) * ldB + n0 + n4] : z4;
            *(float4*)&Bs[k][n4] = v;
        }
        __syncthreads();
#pragma unroll
        for (int k = 0; k < BK; k++) {
            float a[TM], b[TN];
            if constexpr (TM % 4 == 0) {
#pragma unroll
                for (int i = 0; i < TM; i += 4) {
                    float4 v = *(const float4*)&As[k][ty * TM + i];
                    a[i] = v.x; a[i+1] = v.y; a[i+2] = v.z; a[i+3] = v.w;
                }
            } else {
                float2 v = *(const float2*)&As[k][ty * TM];
                a[0] = v.x; a[1] = v.y;
            }
            if constexpr (TN == 4) {
                float4 v = *(const float4*)&Bs[k][tx * 4];
                b[0] = v.x; b[1] = v.y; b[2] = v.z; b[3] = v.w;
            } else {
                float2 v = *(const float2*)&Bs[k][tx * 2];
                b[0] = v.x; b[1] = v.y;
            }
#pragma unroll
            for (int i = 0; i < TM; i++)
#pragma unroll
                for (int j = 0; j < TN; j++) acc[i][j] += a[i] * b[j];
        }
        __syncthreads();
    }
}

__device__ __forceinline__ void gk128(const float* __restrict__ A, const float* __restrict__ B,
                                      int K, int ldA, int ldB, int m0, int n0,
                                      float (&acc)[8][8], float* sm)
{
    float (*As)[128] = (float (*)[128])sm;
    float (*Bs)[128] = (float (*)[128])(sm + 16 * 128);
    const int tid = threadIdx.x;
    const int tx = tid % 16, ty = tid / 16;
    const float4 z4 = make_float4(0.f, 0.f, 0.f, 0.f);
    for (int k0 = 0; k0 < K; k0 += 16) {
#pragma unroll
        for (int i = 0; i < 2; i++) {
            int li = tid + i * 256, k = li / 32, m4 = (li % 32) * 4;
            float4 va = (k0 + k < K) ? *(const float4*)&A[(size_t)(k0 + k) * ldA + m0 + m4] : z4;
            *(float4*)&As[k][m4] = va;
            float4 vb = (k0 + k < K) ? *(const float4*)&B[(size_t)(k0 + k) * ldB + n0 + m4] : z4;
            *(float4*)&Bs[k][m4] = vb;
        }
        __syncthreads();
#pragma unroll
        for (int k = 0; k < 16; k++) {
            float a[8], b[8];
            float4 v0 = *(const float4*)&As[k][ty * 8];
            float4 v1 = *(const float4*)&As[k][ty * 8 + 4];
            a[0]=v0.x; a[1]=v0.y; a[2]=v0.z; a[3]=v0.w; a[4]=v1.x; a[5]=v1.y; a[6]=v1.z; a[7]=v1.w;
            float4 w0 = *(const float4*)&Bs[k][tx * 8];
            float4 w1 = *(const float4*)&Bs[k][tx * 8 + 4];
            b[0]=w0.x; b[1]=w0.y; b[2]=w0.z; b[3]=w0.w; b[4]=w1.x; b[5]=w1.y; b[6]=w1.z; b[7]=w1.w;
#pragma unroll
            for (int i = 0; i < 8; i++)
#pragma unroll
                for (int j = 0; j < 8; j++) acc[i][j] += a[i] * b[j];
        }
        __syncthreads();
    }
}

// --------------------------- one-time precompute ---------------------------
__global__ void k_tr(const float* __restrict__ in, float* __restrict__ out, int M, int K)
{
    __shared__ float tl[32][33];
    int k0 = blockIdx.x * 32, m0 = blockIdx.y * 32;
    int tx = threadIdx.x, ty = threadIdx.y;
    for (int i = ty; i < 32; i += 8)
        if (m0 + i < M && k0 + tx < K) tl[i][tx] = in[(size_t)(m0 + i) * K + k0 + tx];
    __syncthreads();
    for (int i = ty; i < 32; i += 8)
        if (k0 + i < K && m0 + tx < M) out[(size_t)(k0 + i) * M + m0 + tx] = tl[tx][i];
}

__global__ void k_permii(const float* __restrict__ w_ii)
{
    int idx = blockIdx.x * 256 + threadIdx.x;
    if (idx >= GATE_M * IN_D) return;
    int p = idx >> 9, k = idx & 511;
    int m = (p & 3) * H_D + (p >> 2);
    __nv_bfloat16 h, l;
    bsplit(w_ii[(size_t)m * IN_D + k], h, l);
    g_wiih[idx] = h; g_wiil[idx] = l;
}

__global__ void __launch_bounds__(256)
k_w2(const float* __restrict__ w_hi, const float* __restrict__ w_ht)
{
    __shared__ float sm[16 * 128];
    int n0 = blockIdx.x * 64, m0 = blockIdx.y * 64;
    float acc[4][4] = {};
    gk<64,64,16,4,4>(g_wtiT, w_ht, H_D, TI_M, H_D, m0, n0, acc, sm);
    int tx = threadIdx.x % 16, ty = threadIdx.x / 16;
#pragma unroll
    for (int i = 0; i < 4; i++) {
        int m = m0 + ty * 4 + i;
        int p = (m & 511) * 4 + (m >> 9);
#pragma unroll
        for (int j = 0; j < 4; j++) {
            int jc = n0 + tx * 4 + j;
            g_wfT[(size_t)jc * GATE_M + p] = acc[i][j] + w_hi[(size_t)m * H_D + jc];
        }
    }
}

__global__ void k_fillo(const float* __restrict__ w_hi)
{
    int idx = blockIdx.x * 256 + threadIdx.x;
    if (idx >= H_D * H_D) return;
    int r = idx >> 9, j = idx & 511;
    g_wfT[(size_t)j * GATE_M + 4 * r + 3] = w_hi[(size_t)(3 * H_D + r) * H_D + j];
}

// A_tc = [w_ti@w_lmt | w_ti@w_post | w_ti@w_capt] bf16 splits [m][KE], + vc
__global__ void k_small(const float* __restrict__ w_lmt, const float* __restrict__ w_post,
                        const float* __restrict__ w_capt, const float* __restrict__ b_i)
{
    int idx = blockIdx.x * 256 + threadIdx.x;
    if (idx < TI_M * KE) {
        int m = idx / KE, col = idx % KE;
        float s = 0.f;
        if (col < LM_D) {
            for (int k = 0; k < H_D; k++) s += g_wtiT[(size_t)k * TI_M + m] * w_lmt[k * LM_D + col];
        } else if (col < LM_D + POS_D) {
            int l = col - LM_D;
            for (int k = 0; k < H_D; k++) s += g_wtiT[(size_t)k * TI_M + m] * w_post[k * POS_D + l];
        } else if (col < LM_D + POS_D + CAP_D) {
            int l = col - LM_D - POS_D;
            for (int k = 0; k < H_D; k++) s += g_wtiT[(size_t)k * TI_M + m] * w_capt[k * CAP_D + l];
        }
        __nv_bfloat16 hh, ll;
        bsplit(s, hh, ll);
        g_AtcH[idx] = hh; g_AtcL[idx] = ll;
    } else if (idx < TI_M * KE + TI_M) {
        int m = idx - TI_M * KE;
        float s = 0.f;
        for (int k = 0; k < H_D; k++) s += g_wtiT[(size_t)k * TI_M + m] * b_i[4 * H_D + k];
        g_vc[m] = s;
    }
}

// A_ts = [w_ht | w_lmt | w_post | w_capt] bf16 splits [h][KT]
__global__ void k_Ats(const float* __restrict__ w_ht, const float* __restrict__ w_lmt,
                      const float* __restrict__ w_post, const float* __restrict__ w_capt)
{
    int idx = blockIdx.x * 256 + threadIdx.x;
    if (idx >= H_D * KT) return;
    int h = idx / KT, k = idx % KT;
    float v = 0.f;
    if (k < 512)                         v = w_ht [(size_t)h * H_D   + k];
    else if (k < 512 + LM_D)             v = w_lmt[(size_t)h * LM_D  + k - 512];
    else if (k < 512 + LM_D + POS_D)     v = w_post[(size_t)h * POS_D + k - 512 - LM_D];
    else if (k < 512 + LM_D + POS_D + CAP_D) v = w_capt[(size_t)h * CAP_D + k - 512 - LM_D - POS_D];
    __nv_bfloat16 hh, ll;
    bsplit(v, hh, ll);
    g_AtsH[idx] = hh; g_AtsL[idx] = ll;
}

// emb^T splits into g_bT cols 512..735
__global__ void k_embT(const float* __restrict__ lms, const float* __restrict__ poses,
                       const float* __restrict__ caps)
{
    __shared__ float tl[32][33];
    int t = blockIdx.y, b0 = blockIdx.x * 32;
    int tx = threadIdx.x, ty = threadIdx.y;
    for (int l0 = 0; l0 < KE; l0 += 32) {
        for (int i = ty; i < 32; i += 8) {
            int l = l0 + i;
            float v = 0.f;
            if (l < LM_D)                    v = lms  [((size_t)t * LM_D  + l) * B_D + b0 + tx];
            else if (l < LM_D + POS_D)       v = poses[((size_t)t * POS_D + l - LM_D) * B_D + b0 + tx];
            else if (l < LM_D + POS_D + CAP_D) v = caps[((size_t)t * CAP_D + l - LM_D - POS_D) * B_D + b0 + tx];
            tl[i][tx] = v;
        }
        __syncthreads();
        for (int i = ty; i < 32; i += 8) {
            __nv_bfloat16 hh, ll;
            bsplit(tl[tx][i], hh, ll);
            size_t o = ((size_t)t * B_D + b0 + i) * KT + 512 + l0 + tx;
            g_bTh[o] = hh; g_bTl[o] = ll;
        }
        __syncthreads();
    }
}

__global__ void k_init(const float* __restrict__ c0)
{
    int i = blockIdx.x * 256 + threadIdx.x;
    if (i < HB) g_c[i] = c0[i];
    if (i == 0) g_barcnt = 0u;
}

// tiC[0] = w_ti @ t0 (SIMT, single t)
__global__ void __launch_bounds__(256)
k_tiC0(const float* __restrict__ t0)
{
    __shared__ float sm[2 * 16 * 128];
    int m0 = blockIdx.y * 128, n0 = blockIdx.x * 128;
    float acc[8][8] = {};
    gk128(g_wtiT, t0, H_D, TI_M, B_D, m0, n0, acc, sm);
    int tx = threadIdx.x % 16, ty = threadIdx.x / 16;
#pragma unroll
    for (int i = 0; i < 8; i++) {
        int m = m0 + ty * 8 + i;
        size_t idx = (size_t)m * B_D + n0 + tx * 8;
        *(float4*)&g_tiC[idx]     = make_float4(acc[i][0], acc[i][1], acc[i][2], acc[i][3]);
        *(float4*)&g_tiC[idx + 4] = make_float4(acc[i][4], acc[i][5], acc[i][6], acc[i][7]);
    }
}

// ---------------- generic wmma GEMM against g_bT -------------------
// MODE 0: tiC (t = z+1, B = emb cols of t-1, K=KE):  g_tiC = A_tc@emb + vc
// MODE 1: Ts  (t = z,   B = full row of t,   K=KT):  g_Ts = A_ts@[h|emb] + b5 (+ out TS)
template <int MODE>
__global__ void __launch_bounds__(256)
k_wm(const float* __restrict__ bi, float* __restrict__ out)
{
    constexpr int KTOT = MODE ? KT : KE;
    constexpr int BOFS = MODE ? 0 : 512;
    constexpr int LDA  = MODE ? KT : KE;
    __shared__ float es[8][320];
    const int t = MODE ? blockIdx.z : blockIdx.z + 1;
    const int tb = MODE ? t : t - 1;
    const int m0 = blockIdx.x * 128, n0 = blockIdx.y * 128;
    const int wid = threadIdx.x / 32, lane = threadIdx.x % 32;
    const int wr = wid >> 2, wc = wid & 3;
    const __nv_bfloat16* Ah = (MODE ? g_AtsH : g_AtcH) + (size_t)(m0 + wr * 64) * LDA;
    const __nv_bfloat16* Al = (MODE ? g_AtsL : g_AtcL) + (size_t)(m0 + wr * 64) * LDA;
    const __nv_bfloat16* Bh = g_bTh + ((size_t)tb * B_D + n0 + wc * 32) * KT + BOFS;
    const __nv_bfloat16* Bl = g_bTl + ((size_t)tb * B_D + n0 + wc * 32) * KT + BOFS;

    wmma::fragment<wmma::accumulator, 16, 16, 16, float> acc[4][2];
#pragma unroll
    for (int i = 0; i < 4; i++)
#pragma unroll
        for (int j = 0; j < 2; j++) wmma::fill_fragment(acc[i][j], 0.f);

    for (int kk = 0; kk < KTOT; kk += 16) {
        wmma::fragment<wmma::matrix_b, 16, 16, 16, __nv_bfloat16, wmma::col_major> bh[2], bl[2];
#pragma unroll
        for (int j = 0; j < 2; j++) {
            wmma::load_matrix_sync(bh[j], Bh + (size_t)j * 16 * KT + kk, KT);
            wmma::load_matrix_sync(bl[j], Bl + (size_t)j * 16 * KT + kk, KT);
        }
#pragma unroll
        for (int i = 0; i < 4; i++) {
            wmma::fragment<wmma::matrix_a, 16, 16, 16, __nv_bfloat16, wmma::row_major> ah, al;
            wmma::load_matrix_sync(ah, Ah + (size_t)i * 16 * LDA + kk, LDA);
            wmma::load_matrix_sync(al, Al + (size_t)i * 16 * LDA + kk, LDA);
#pragma unroll
            for (int j = 0; j < 2; j++) {
                wmma::mma_sync(acc[i][j], ah, bh[j], acc[i][j]);
                wmma::mma_sync(acc[i][j], ah, bl[j], acc[i][j]);
                wmma::mma_sync(acc[i][j], al, bh[j], acc[i][j]);
            }
        }
    }

#pragma unroll 1
    for (int i = 0; i < 4; i++)
#pragma unroll 1
        for (int j = 0; j < 2; j++) {
            wmma::store_matrix_sync(&es[wid][0], acc[i][j], 20, wmma::mem_row_major);
            __syncwarp();
            int m = m0 + wr * 64 + i * 16, b = n0 + wc * 32 + j * 16;
            int r0 = lane >> 1, c0 = (lane & 1) * 8;
            if (MODE == 0) {
                float add = bi[m + r0];
                float v[8];
#pragma unroll
                for (int q = 0; q < 8; q++) v[q] = es[wid][r0 * 20 + c0 + q] + add;
                float* dst = &g_tiC[((size_t)t * TI_M + m + r0) * B_D + b + c0];
                *(float4*)dst       = make_float4(v[0], v[1], v[2], v[3]);
                *(float4*)(dst + 4) = make_float4(v[4], v[5], v[6], v[7]);
            } else {
                float add = bi[4 * H_D + m + r0];
                float v[8];
#pragma unroll
                for (int q = 0; q < 8; q++) v[q] = es[wid][r0 * 20 + c0 + q] + add;
                float* dst = &g_Ts[((size_t)t * H_D + m + r0) * B_D + b + c0];
                *(float4*)dst       = make_float4(v[0], v[1], v[2], v[3]);
                *(float4*)(dst + 4) = make_float4(v[4], v[5], v[6], v[7]);
                __syncwarp();
                int bc = lane & 15, mh = (lane >> 4) * 8;
                float w[8];
#pragma unroll
                for (int q = 0; q < 8; q++)
                    w[q] = es[wid][(mh + q) * 20 + bc] + bi[4 * H_D + m + mh + q];
                float* od = &out[OFF_TS + ((size_t)(b + bc) * T_STEPS + t) * H_D + m + mh];
                *(float4*)od       = make_float4(w[0], w[1], w[2], w[3]);
                *(float4*)(od + 4) = make_float4(w[4], w[5], w[6], w[7]);
            }
            __syncwarp();
        }
}

// ------------------------------ phase A ------------------------------------
__global__ void __launch_bounds__(256, 2)
k_x(const float* __restrict__ inputs, const float* __restrict__ lms,
    const float* __restrict__ poses, const float* __restrict__ caps,
    const float* __restrict__ w_lmw, const float* __restrict__ w_posw,
    const float* __restrict__ w_capw)
{
    __shared__ float sm[2 * 16 * 128];
    int t = blockIdx.z, m0 = blockIdx.y * 128, n0 = blockIdx.x * 128;
    float acc[8][8] = {};
    gk128(w_lmw,  lms   + (size_t)t * LM_D  * B_D, LM_D,  IN_D, B_D, m0, n0, acc, sm);
    gk128(w_posw, poses + (size_t)t * POS_D * B_D, POS_D, IN_D, B_D, m0, n0, acc, sm);
    gk128(w_capw, caps  + (size_t)t * CAP_D * B_D, CAP_D, IN_D, B_D, m0, n0, acc, sm);
    int tx = threadIdx.x % 16, ty = threadIdx.x / 16;
    size_t base = (size_t)t * IN_D * B_D;
    float xv[8][8];
#pragma unroll
    for (int i = 0; i < 8; i++) {
        size_t idx = base + (size_t)(m0 + ty * 8 + i) * B_D + n0 + tx * 8;
#pragma unroll
        for (int q = 0; q < 2; q++) {
            float4 v = *(const float4*)&inputs[idx + q * 4];
            xv[i][q*4+0] = acc[i][q*4+0] + v.x; xv[i][q*4+1] = acc[i][q*4+1] + v.y;
            xv[i][q*4+2] = acc[i][q*4+2] + v.z; xv[i][q*4+3] = acc[i][q*4+3] + v.w;
        }
    }
#pragma unroll
    for (int j = 0; j < 8; j++) {
        int b = n0 + tx * 8 + j;
        __align__(16) __nv_bfloat16 ah[8], al[8];
#pragma unroll
        for (int i = 0; i < 8; i++) bsplit(xv[i][j], ah[i], al[i]);
        size_t o = ((size_t)t * B_D + b) * IN_D + m0 + ty * 8;
        *(uint4*)&g_xTh[o] = *(uint4*)ah;
        *(uint4*)&g_xTl[o] = *(uint4*)al;
    }
}

// -------- wmma k_ii: g_pre = w_ii@x + tiC + b (unchanged from R10) ---------
#define LDS_K 40
__global__ void __launch_bounds__(256)
k_ii_wm(const float* __restrict__ b_i)
{
    extern __shared__ char dsm[];
    __nv_bfloat16 (*Ah)[LDS_K] = (__nv_bfloat16 (*)[LDS_K])(dsm);
    __nv_bfloat16 (*Al)[LDS_K] = (__nv_bfloat16 (*)[LDS_K])(dsm + 10240);
    __nv_bfloat16 (*Bh)[LDS_K] = (__nv_bfloat16 (*)[LDS_K])(dsm + 20480);
    __nv_bfloat16 (*Bl)[LDS_K] = (__nv_bfloat16 (*)[LDS_K])(dsm + 30720);

    const int t = blockIdx.z, m0 = blockIdx.x * 128, n0 = blockIdx.y * 128;
    const int tid = threadIdx.x, wid = tid / 32, lane = tid % 32;
    const int wr = wid >> 2, wc = wid & 3;

    wmma::fragment<wmma::accumulator, 16, 16, 16, float> acc[4][2];
#pragma unroll
    for (int i = 0; i < 4; i++)
#pragma unroll
        for (int j = 0; j < 2; j++) wmma::fill_fragment(acc[i][j], 0.f);

    const __nv_bfloat16* wh = g_wiih + (size_t)m0 * IN_D;
    const __nv_bfloat16* wl = g_wiil + (size_t)m0 * IN_D;
    const __nv_bfloat16* xh = g_xTh + ((size_t)t * B_D + n0) * IN_D;
    const __nv_bfloat16* xl = g_xTl + ((size_t)t * B_D + n0) * IN_D;

    for (int ch = 0; ch < 16; ch++) {
#pragma unroll
        for (int it = 0; it < 2; it++) {
            int s = tid + it * 256, r = s >> 2, kq = (s & 3) * 8;
            *(uint4*)&Ah[r][kq] = *(const uint4*)(wh + (size_t)r * IN_D + ch * 32 + kq);
            *(uint4*)&Al[r][kq] = *(const uint4*)(wl + (size_t)r * IN_D + ch * 32 + kq);
            *(uint4*)&Bh[r][kq] = *(const uint4*)(xh + (size_t)r * IN_D + ch * 32 + kq);
            *(uint4*)&Bl[r][kq] = *(const uint4*)(xl + (size_t)r * IN_D + ch * 32 + kq);
        }
        __syncthreads();
#pragma unroll
        for (int kk = 0; kk < 2; kk++) {
            wmma::fragment<wmma::matrix_b, 16, 16, 16, __nv_bfloat16, wmma::col_major> bh[2], bl[2];
#pragma unroll
            for (int j = 0; j < 2; j++) {
                wmma::load_matrix_sync(bh[j], &Bh[wc * 32 + j * 16][kk * 16], LDS_K);
                wmma::load_matrix_sync(bl[j], &Bl[wc * 32 + j * 16][kk * 16], LDS_K);
            }
#pragma unroll
            for (int i = 0; i < 4; i++) {
                wmma::fragment<wmma::matrix_a, 16, 16, 16, __nv_bfloat16, wmma::row_major> ah, al;
                wmma::load_matrix_sync(ah, &Ah[wr * 64 + i * 16][kk * 16], LDS_K);
                wmma::load_matrix_sync(al, &Al[wr * 64 + i * 16][kk * 16], LDS_K);
#pragma unroll
                for (int j = 0; j < 2; j++) {
                    wmma::mma_sync(acc[i][j], ah, bh[j], acc[i][j]);
                    wmma::mma_sync(acc[i][j], ah, bl[j], acc[i][j]);
                    wmma::mma_sync(acc[i][j], al, bh[j], acc[i][j]);
                }
            }
        }
        __syncthreads();
    }

    float (*eb)[20] = (float (*)[20])(dsm + wid * 1280);
    size_t preb = (size_t)t * GATE_M * B_D;
    size_t tib  = (size_t)t * TI_M * B_D;
#pragma unroll 1
    for (int i = 0; i < 4; i++)
#pragma unroll 1
        for (int j = 0; j < 2; j++) {
            wmma::store_matrix_sync(&eb[0][0], acc[i][j], 20, wmma::mem_row_major);
            __syncwarp();
            int r0 = lane >> 1, c0 = (lane & 1) * 8;
            int p = m0 + wr * 64 + i * 16 + r0;
            int b = n0 + wc * 32 + j * 16 + c0;
            int g = p & 3, rr = p >> 2;
            float add = b_i[g * H_D + rr];
            float v[8];
#pragma unroll
            for (int q = 0; q < 8; q++) v[q] = eb[r0][c0 + q] + add;
            if (g < 3) {
                const float* tc = &g_tiC[tib + (size_t)(g * H_D + rr) * B_D + b];
#pragma unroll
                for (int q = 0; q < 8; q++) v[q] += tc[q];
            }
            float* dst = &g_pre[preb + (size_t)p * B_D + b];
            *(float4*)dst       = make_float4(v[0], v[1], v[2], v[3]);
            *(float4*)(dst + 4) = make_float4(v[4], v[5], v[6], v[7]);
            __syncwarp();
        }
}

// --------------------- persistent serial loop ------------------------------
__device__ __forceinline__ void grid_bar(unsigned target)
{
    __syncthreads();
    if (threadIdx.x == 0) {
        __threadfence();
        atomicAdd(&g_barcnt, 1u);
        while (*((volatile unsigned*)&g_barcnt) < target) __nanosleep(64);
    }
    __syncthreads();
    __threadfence();
}

__global__ void __launch_bounds__(256)
k_loop(const float* __restrict__ h0)
{
    __shared__ float sm[2048];
    const int cta = blockIdx.x;
    const int tx = threadIdx.x % 16, ty = threadIdx.x / 16;
    unsigned gen = 0;

    for (int t = 0; t < T_STEPS; t++) {
        const float* hprev = (t == 0) ? h0 : (g_hall + (size_t)(t - 1) * HB);
        {
            int m0 = (cta >> 2) * 64, n0 = (cta & 3) * 64;
            float acc[4][4] = {};
            gk<64,64,16,4,4>(g_wfT, hprev, H_D, GATE_M, B_D, m0, n0, acc, sm);
            int r = (m0 + ty * 4) >> 2;
            int col = n0 + tx * 4;
            size_t base = (size_t)t * GATE_M * B_D + (size_t)(m0 + ty * 4) * B_D + col;
            float4 pi = *(const float4*)&g_pre[base];
            float4 pf = *(const float4*)&g_pre[base + B_D];
            float4 pz = *(const float4*)&g_pre[base + 2 * B_D];
            float4 po = *(const float4*)&g_pre[base + 3 * B_D];
            float4 co = *(const float4*)&g_c[r * B_D + col];
            float pia[4] = {pi.x, pi.y, pi.z, pi.w}, pfa[4] = {pf.x, pf.y, pf.z, pf.w};
            float pza[4] = {pz.x, pz.y, pz.z, pz.w}, poa[4] = {po.x, po.y, po.z, po.w};
            float coa[4] = {co.x, co.y, co.z, co.w};
            float cn[4], op[4];
#pragma unroll
            for (int j = 0; j < 4; j++) {
                float ig = sigm(acc[0][j] + pia[j]);
                float fg = sigm(acc[1][j] + pfa[j]);
                float zg = tanhf(acc[2][j] + pza[j]);
                cn[j] = fg * coa[j] + ig * zg;
                op[j] = acc[3][j] + poa[j];
            }
            *(float4*)&g_c[r * B_D + col]    = make_float4(cn[0], cn[1], cn[2], cn[3]);
            *(float4*)&g_opre[r * B_D + col] = make_float4(op[0], op[1], op[2], op[3]);
        }
        grid_bar(++gen * NCTA);
        {
            int m0 = (cta >> 3) * 32, n0 = (cta & 7) * 32;
            float acc[2][2] = {};
            gk<32,32,32,2,2>(g_wcoT, g_c, H_D, H_D, B_D, m0, n0, acc, sm);
            size_t hb = (size_t)t * HB;
            float (*hs)[33] = (float (*)[33])sm;
#pragma unroll
            for (int i = 0; i < 2; i++)
#pragma unroll
                for (int j = 0; j < 2; j++) {
                    int lr = ty * 2 + i, lb = tx * 2 + j;
                    int rb = (m0 + lr) * B_D + n0 + lb;
                    float o = sigm(acc[i][j] + g_opre[rb]);
                    float hv = o * tanhf(g_c[rb]);
                    g_hall[hb + rb] = hv;
                    hs[lr][lb] = hv;
                }
            __syncthreads();
            {
                int r2 = threadIdx.x >> 3, c4 = (threadIdx.x & 7) * 4;   // b-row, r-col4
                __nv_bfloat16 hh[4], ll[4];
#pragma unroll
                for (int q = 0; q < 4; q++) bsplit(hs[c4 + q][r2], hh[q], ll[q]);
                size_t o = ((size_t)t * B_D + n0 + r2) * KT + m0 + c4;
                *(uint2*)&g_bTh[o] = *(uint2*)hh;
                *(uint2*)&g_bTl[o] = *(uint2*)ll;
            }
        }
        grid_bar(++gen * NCTA);
    }
}

// ------------------------------ k_y (unchanged) -----------------------------
__global__ void __launch_bounds__(256)
k_y(const float* __restrict__ byf, const float* __restrict__ byc, float* __restrict__ out)
{
    __shared__ float sm[2 * 64 * 68];
    int t = blockIdx.y, n0 = blockIdx.x * 64;
    const float* Tst = g_Ts + (size_t)t * HB;
    float aF[4][4] = {}, aC[4][4] = {};
    gk<64,64,16,4,4>(g_wyfT, Tst, H_D, TAG, B_D, 0, n0, aF, sm);
    gk<64,64,16,4,4>(g_wycT, Tst, H_D, TAG, B_D, 0, n0, aC, sm);
    float (*yF)[68] = (float (*)[68])sm;
    float (*yC)[68] = (float (*)[68])(sm + 64 * 68);
    int tx = threadIdx.x % 16, ty = threadIdx.x / 16;
#pragma unroll
    for (int i = 0; i < 4; i++)
#pragma unroll
        for (int j = 0; j < 4; j++) {
            int m = ty * 4 + i, n = tx * 4 + j;
            yF[m][n] = aF[i][j] + byf[m];
            yC[m][n] = aC[i][j] + byc[m];
        }
    __syncthreads();
    if (threadIdx.x < 64) {
        int col = threadIdx.x, b = n0 + col;
        float mxF = -1e30f, mxC = -1e30f;
#pragma unroll
        for (int m = 0; m < TAG; m++) {
            mxF = fmaxf(mxF, yF[m][col]);
            mxC = fmaxf(mxC, yC[m][col]);
        }
        float sF = 0.f, sC = 0.f;
#pragma unroll
        for (int m = 0; m < TAG; m++) {
            sF += expf(yF[m][col] - mxF);
            sC += expf(yC[m][col] - mxC);
        }
        float lseF = mxF + logf(sF), lseC = mxC + logf(sC);
        size_t base = ((size_t)b * T_STEPS + t) * TAG;
#pragma unroll
        for (int m = 0; m < TAG; m++) {
            float vf = yF[m][col], vc = yC[m][col];
            out[OFF_LF + base + m] = vf - lseF;
            out[OFF_LC + base + m] = vc - lseC;
            out[OFF_YF + base + m] = vf;
            out[OFF_YC + base + m] = vc;
        }
    }
}

// ------------------------------- launch ------------------------------------
extern "C" void kernel_launch(void* const* d_in, const int* in_sizes, int n_in,
                              void* d_out, int out_size)
{
    const float* inputs   = (const float*)d_in[0];
    const float* lms      = (const float*)d_in[1];
    const float* poses    = (const float*)d_in[2];
    const float* caps     = (const float*)d_in[3];
    const float* h0       = (const float*)d_in[4];
    const float* c0       = (const float*)d_in[5];
    const float* t0       = (const float*)d_in[6];
    const float* w_ii     = (const float*)d_in[7];
    const float* w_hi     = (const float*)d_in[8];
    const float* w_ti     = (const float*)d_in[9];
    const float* w_co     = (const float*)d_in[10];
    const float* w_ht     = (const float*)d_in[11];
    const float* b_i      = (const float*)d_in[12];
    const float* b_y_fact = (const float*)d_in[14];
    const float* b_y_cond = (const float*)d_in[16];
    const float* w_lmw    = (const float*)d_in[17];
    const float* w_posw   = (const float*)d_in[18];
    const float* w_capw   = (const float*)d_in[19];
    const float* w_lmt    = (const float*)d_in[20];
    const float* w_post   = (const float*)d_in[21];
    const float* w_capt   = (const float*)d_in[22];
    float* out = (float*)d_out;

    float *pwti, *pwco, *pyf, *pyc, *pvc;
    cudaGetSymbolAddress((void**)&pwti, g_wtiT);
    cudaGetSymbolAddress((void**)&pwco, g_wcoT);
    cudaGetSymbolAddress((void**)&pyf,  g_wyfT);
    cudaGetSymbolAddress((void**)&pyc,  g_wycT);
    cudaGetSymbolAddress((void**)&pvc,  g_vc);
    dim3 tb(32, 8);

    // launch index 5 = k_wm<0> (profiled by ncu -s 5 -c 1)
    k_embT <<<dim3(8, T_STEPS), tb>>>(lms, poses, caps);                     // 0
    k_tr   <<<dim3(16, 48), tb>>>(w_ti, pwti, TI_M, H_D);                    // 1
    k_small<<<(TI_M * (KE + 1) + 255) / 256, 256>>>(w_lmt, w_post, w_capt, b_i); // 2
    k_tiC0 <<<dim3(2, 12), 256>>>(t0);                                       // 3
    k_permii<<<(GATE_M * IN_D) / 256, 256>>>(w_ii);                          // 4
    k_wm<0><<<dim3(12, 2, T_STEPS - 1), 256>>>(pvc, nullptr);                // 5
    k_x    <<<dim3(2, 4, T_STEPS), 256>>>(inputs, lms, poses, caps, w_lmw, w_posw, w_capw);
    k_ii_wm<<<dim3(16, 2, T_STEPS), 256, 40960>>>(b_i);

    k_tr   <<<dim3(16, 16), tb>>>(w_co, pwco, H_D, H_D);
    k_w2   <<<dim3(8, 24), 256>>>(w_hi, w_ht);
    k_fillo<<<1024, 256>>>(w_hi);
    k_init <<<HB / 256, 256>>>(c0);
    k_Ats  <<<(H_D * KT + 255) / 256, 256>>>(w_ht, w_lmt, w_post, w_capt);

    k_loop <<<NCTA, 256>>>(h0);

    k_wm<1><<<dim3(4, 2, T_STEPS), 256>>>(b_i, out);
    k_tr   <<<dim3(16, 2), tb>>>((const float*)d_in[13], pyf, TAG, H_D);
    k_tr   <<<dim3(16, 2), tb>>>((const float*)d_in[15], pyc, TAG, H_D);
    k_y    <<<dim3(4, T_STEPS), 256>>>(b_y_fact, b_y_cond, out);
}

// round 14
// speedup vs baseline: 1.4299x; 1.3058x over previous
#include <cuda_runtime.h>
#include <cuda_bf16.h>
#include <mma.h>
#include <math.h>
#include <stdint.h>

using namespace nvcuda;

#define T_STEPS 128
#define IN_D    512
#define H_D     512
#define B_D     256
#define TAG     64
#define LM_D    200
#define POS_D   6
#define CAP_D   3
#define HB      (H_D * B_D)
#define GATE_M  (4 * H_D)
#define TI_M    (3 * H_D)
#define NCTA    128
#define KE      224
#define KT      736

#define SEC_Y   ((size_t)B_D * T_STEPS * TAG)
#define OFF_LF  ((size_t)0)
#define OFF_LC  (SEC_Y)
#define OFF_YF  (2 * SEC_Y)
#define OFF_YC  (3 * SEC_Y)
#define OFF_TS  (4 * SEC_Y)

// ------------------------- scratch (device globals) -------------------------
__device__ float g_pre  [(size_t)T_STEPS * GATE_M * B_D];
__device__ float g_tiC  [(size_t)T_STEPS * TI_M   * B_D];
__device__ float g_Ts   [(size_t)T_STEPS * H_D    * B_D];
__device__ float g_c    [HB];
__device__ float g_opre [HB];
__device__ unsigned g_barcnt;
// bf16 split operands
__device__ __nv_bfloat16 g_wiih[(size_t)GATE_M * IN_D];
__device__ __nv_bfloat16 g_wiil[(size_t)GATE_M * IN_D];
__device__ __nv_bfloat16 g_wfh [(size_t)GATE_M * H_D];    // folded Wf, permuted p, row-major
__device__ __nv_bfloat16 g_wfl [(size_t)GATE_M * H_D];
__device__ __nv_bfloat16 g_xTh [(size_t)T_STEPS * B_D * IN_D];
__device__ __nv_bfloat16 g_xTl [(size_t)T_STEPS * B_D * IN_D];
__device__ __nv_bfloat16 g_bTh [(size_t)T_STEPS * B_D * KT];   // [t][b][ h(512) | emb(224) ]
__device__ __nv_bfloat16 g_bTl [(size_t)T_STEPS * B_D * KT];
__device__ __nv_bfloat16 g_h0Th[(size_t)B_D * KT];
__device__ __nv_bfloat16 g_h0Tl[(size_t)B_D * KT];
__device__ __nv_bfloat16 g_AtsH[(size_t)H_D * KT];
__device__ __nv_bfloat16 g_AtsL[(size_t)H_D * KT];
__device__ __nv_bfloat16 g_AtcH[(size_t)TI_M * KE];
__device__ __nv_bfloat16 g_AtcL[(size_t)TI_M * KE];
// fp32 k-major weights still used
__device__ float g_wtiT [(size_t)H_D * TI_M];
__device__ float g_wcoT [(size_t)H_D * H_D];
__device__ float g_wyfT [(size_t)H_D * TAG];
__device__ float g_wycT [(size_t)H_D * TAG];
__device__ float g_vc   [TI_M];

__device__ __forceinline__ float sigm(float x) { return 1.f / (1.f + expf(-x)); }
__device__ __forceinline__ void bsplit(float v, __nv_bfloat16& h, __nv_bfloat16& l)
{
    h = __float2bfloat16_rn(v);
    l = __float2bfloat16_rn(v - __bfloat162float(h));
}

// ---------------------------------------------------------------------------
// SIMT GEMM cores
// ---------------------------------------------------------------------------
template <int BM, int BN, int BK, int TM, int TN>
__device__ __forceinline__ void gk(const float* __restrict__ A, const float* __restrict__ B,
                                   int K, int ldA, int ldB, int m0, int n0,
                                   float (&acc)[TM][TN], float* sm)
{
    float (*As)[BM] = (float (*)[BM])sm;
    float (*Bs)[BN] = (float (*)[BN])(sm + BK * BM);
    const int tid = threadIdx.x;
    const int tx = tid % (BN / TN), ty = tid / (BN / TN);
    constexpr int AV = BM / 4, BV = BN / 4;
    constexpr int AL = (BM * BK / 4) / 256, BL = (BN * BK / 4) / 256;
    const float4 z4 = make_float4(0.f, 0.f, 0.f, 0.f);
    for (int k0 = 0; k0 < K; k0 += BK) {
#pragma unroll
        for (int i = 0; i < AL; i++) {
            int li = tid + i * 256, k = li / AV, m4 = (li % AV) * 4;
            float4 v = (k0 + k < K) ? *(const float4*)&A[(size_t)(k0 + k) * ldA + m0 + m4] : z4;
            *(float4*)&As[k][m4] = v;
        }
#pragma unroll
        for (int i = 0; i < BL; i++) {
            int li = tid + i * 256, k = li / BV, n4 = (li % BV) * 4;
            float4 v = (k0 + k < K) ? *(const float4*)&B[(size_t)(k0 + k) * ldB + n0 + n4] : z4;
            *(float4*)&Bs[k][n4] = v;
        }
        __syncthreads();
#pragma unroll
        for (int k = 0; k < BK; k++) {
            float a[TM], b[TN];
            if constexpr (TM % 4 == 0) {
#pragma unroll
                for (int i = 0; i < TM; i += 4) {
                    float4 v = *(const float4*)&As[k][ty * TM + i];
                    a[i] = v.x; a[i+1] = v.y; a[i+2] = v.z; a[i+3] = v.w;
                }
            } else {
                float2 v = *(const float2*)&As[k][ty * TM];
                a[0] = v.x; a[1] = v.y;
            }
            if constexpr (TN == 4) {
                float4 v = *(const float4*)&Bs[k][tx * 4];
                b[0] = v.x; b[1] = v.y; b[2] = v.z; b[3] = v.w;
            } else {
                float2 v = *(const float2*)&Bs[k][tx * 2];
                b[0] = v.x; b[1] = v.y;
            }
#pragma unroll
            for (int i = 0; i < TM; i++)
#pragma unroll
                for (int j = 0; j < TN; j++) acc[i][j] += a[i] * b[j];
        }
        __syncthreads();
    }
}

__device__ __forceinline__ void gk128(const float* __restrict__ A, const float* __restrict__ B,
                                      int K, int ldA, int ldB, int m0, int n0,
                                      float (&acc)[8][8], float* sm)
{
    float (*As)[128] = (float (*)[128])sm;
    float (*Bs)[128] = (float (*)[128])(sm + 16 * 128);
    const int tid = threadIdx.x;
    const int tx = tid % 16, ty = tid / 16;
    const float4 z4 = make_float4(0.f, 0.f, 0.f, 0.f);
    for (int k0 = 0; k0 < K; k0 += 16) {
#pragma unroll
        for (int i = 0; i < 2; i++) {
            int li = tid + i * 256, k = li / 32, m4 = (li % 32) * 4;
            float4 va = (k0 + k < K) ? *(const float4*)&A[(size_t)(k0 + k) * ldA + m0 + m4] : z4;
            *(float4*)&As[k][m4] = va;
            float4 vb = (k0 + k < K) ? *(const float4*)&B[(size_t)(k0 + k) * ldB + n0 + m4] : z4;
            *(float4*)&Bs[k][m4] = vb;
        }
        __syncthreads();
#pragma unroll
        for (int k = 0; k < 16; k++) {
            float a[8], b[8];
            float4 v0 = *(const float4*)&As[k][ty * 8];
            float4 v1 = *(const float4*)&As[k][ty * 8 + 4];
            a[0]=v0.x; a[1]=v0.y; a[2]=v0.z; a[3]=v0.w; a[4]=v1.x; a[5]=v1.y; a[6]=v1.z; a[7]=v1.w;
            float4 w0 = *(const float4*)&Bs[k][tx * 8];
            float4 w1 = *(const float4*)&Bs[k][tx * 8 + 4];
            b[0]=w0.x; b[1]=w0.y; b[2]=w0.z; b[3]=w0.w; b[4]=w1.x; b[5]=w1.y; b[6]=w1.z; b[7]=w1.w;
#pragma unroll
            for (int i = 0; i < 8; i++)
#pragma unroll
                for (int j = 0; j < 8; j++) acc[i][j] += a[i] * b[j];
        }
        __syncthreads();
    }
}

// --------------------------- one-time precompute ---------------------------
__global__ void k_tr(const float* __restrict__ in, float* __restrict__ out, int M, int K)
{
    __shared__ float tl[32][33];
    int k0 = blockIdx.x * 32, m0 = blockIdx.y * 32;
    int tx = threadIdx.x, ty = threadIdx.y;
    for (int i = ty; i < 32; i += 8)
        if (m0 + i < M && k0 + tx < K) tl[i][tx] = in[(size_t)(m0 + i) * K + k0 + tx];
    __syncthreads();
    for (int i = ty; i < 32; i += 8)
        if (k0 + i < K && m0 + tx < M) out[(size_t)(k0 + i) * M + m0 + tx] = tl[tx][i];
}

__global__ void k_permii(const float* __restrict__ w_ii)
{
    int idx = blockIdx.x * 256 + threadIdx.x;
    if (idx >= GATE_M * IN_D) return;
    int p = idx >> 9, k = idx & 511;
    int m = (p & 3) * H_D + (p >> 2);
    __nv_bfloat16 h, l;
    bsplit(w_ii[(size_t)m * IN_D + k], h, l);
    g_wiih[idx] = h; g_wiil[idx] = l;
}

// Wf = w_hi[ifz] + w_ti@w_ht -> bf16 splits, permuted rows, row-major [p][j]
__global__ void __launch_bounds__(256)
k_w2(const float* __restrict__ w_hi, const float* __restrict__ w_ht)
{
    __shared__ float sm[16 * 128];
    int n0 = blockIdx.x * 64, m0 = blockIdx.y * 64;
    float acc[4][4] = {};
    gk<64,64,16,4,4>(g_wtiT, w_ht, H_D, TI_M, H_D, m0, n0, acc, sm);
    int tx = threadIdx.x % 16, ty = threadIdx.x / 16;
#pragma unroll
    for (int i = 0; i < 4; i++) {
        int m = m0 + ty * 4 + i;
        int p = (m & 511) * 4 + (m >> 9);
#pragma unroll
        for (int j = 0; j < 4; j++) {
            int jc = n0 + tx * 4 + j;
            __nv_bfloat16 hh, ll;
            bsplit(acc[i][j] + w_hi[(size_t)m * H_D + jc], hh, ll);
            g_wfh[(size_t)p * H_D + jc] = hh;
            g_wfl[(size_t)p * H_D + jc] = ll;
        }
    }
}

__global__ void k_fillo(const float* __restrict__ w_hi)
{
    int idx = blockIdx.x * 256 + threadIdx.x;
    if (idx >= H_D * H_D) return;
    int r = idx >> 9, j = idx & 511;
    __nv_bfloat16 hh, ll;
    bsplit(w_hi[(size_t)(3 * H_D + r) * H_D + j], hh, ll);
    g_wfh[(size_t)(4 * r + 3) * H_D + j] = hh;
    g_wfl[(size_t)(4 * r + 3) * H_D + j] = ll;
}

__global__ void k_small(const float* __restrict__ w_lmt, const float* __restrict__ w_post,
                        const float* __restrict__ w_capt, const float* __restrict__ b_i)
{
    int idx = blockIdx.x * 256 + threadIdx.x;
    if (idx < TI_M * KE) {
        int m = idx / KE, col = idx % KE;
        float s = 0.f;
        if (col < LM_D) {
            for (int k = 0; k < H_D; k++) s += g_wtiT[(size_t)k * TI_M + m] * w_lmt[k * LM_D + col];
        } else if (col < LM_D + POS_D) {
            int l = col - LM_D;
            for (int k = 0; k < H_D; k++) s += g_wtiT[(size_t)k * TI_M + m] * w_post[k * POS_D + l];
        } else if (col < LM_D + POS_D + CAP_D) {
            int l = col - LM_D - POS_D;
            for (int k = 0; k < H_D; k++) s += g_wtiT[(size_t)k * TI_M + m] * w_capt[k * CAP_D + l];
        }
        __nv_bfloat16 hh, ll;
        bsplit(s, hh, ll);
        g_AtcH[idx] = hh; g_AtcL[idx] = ll;
    } else if (idx < TI_M * KE + TI_M) {
        int m = idx - TI_M * KE;
        float s = 0.f;
        for (int k = 0; k < H_D; k++) s += g_wtiT[(size_t)k * TI_M + m] * b_i[4 * H_D + k];
        g_vc[m] = s;
    }
}

__global__ void k_Ats(const float* __restrict__ w_ht, const float* __restrict__ w_lmt,
                      const float* __restrict__ w_post, const float* __restrict__ w_capt)
{
    int idx = blockIdx.x * 256 + threadIdx.x;
    if (idx >= H_D * KT) return;
    int h = idx / KT, k = idx % KT;
    float v = 0.f;
    if (k < 512)                         v = w_ht [(size_t)h * H_D   + k];
    else if (k < 512 + LM_D)             v = w_lmt[(size_t)h * LM_D  + k - 512];
    else if (k < 512 + LM_D + POS_D)     v = w_post[(size_t)h * POS_D + k - 512 - LM_D];
    else if (k < 512 + LM_D + POS_D + CAP_D) v = w_capt[(size_t)h * CAP_D + k - 512 - LM_D - POS_D];
    __nv_bfloat16 hh, ll;
    bsplit(v, hh, ll);
    g_AtsH[idx] = hh; g_AtsL[idx] = ll;
}

__global__ void k_embT(const float* __restrict__ lms, const float* __restrict__ poses,
                       const float* __restrict__ caps)
{
    __shared__ float tl[32][33];
    int t = blockIdx.y, b0 = blockIdx.x * 32;
    int tx = threadIdx.x, ty = threadIdx.y;
    for (int l0 = 0; l0 < KE; l0 += 32) {
        for (int i = ty; i < 32; i += 8) {
            int l = l0 + i;
            float v = 0.f;
            if (l < LM_D)                    v = lms  [((size_t)t * LM_D  + l) * B_D + b0 + tx];
            else if (l < LM_D + POS_D)       v = poses[((size_t)t * POS_D + l - LM_D) * B_D + b0 + tx];
            else if (l < LM_D + POS_D + CAP_D) v = caps[((size_t)t * CAP_D + l - LM_D - POS_D) * B_D + b0 + tx];
            tl[i][tx] = v;
        }
        __syncthreads();
        for (int i = ty; i < 32; i += 8) {
            __nv_bfloat16 hh, ll;
            bsplit(tl[tx][i], hh, ll);
            size_t o = ((size_t)t * B_D + b0 + i) * KT + 512 + l0 + tx;
            g_bTh[o] = hh; g_bTl[o] = ll;
        }
        __syncthreads();
    }
}

// h0 (h,b) -> g_h0T [b][h] bf16 splits (ld KT)
__global__ void k_h0T(const float* __restrict__ h0)
{
    __shared__ float tl[32][33];
    int b0 = blockIdx.x * 32, h0t = blockIdx.y * 32;
    int tx = threadIdx.x, ty = threadIdx.y;
    for (int i = ty; i < 32; i += 8)
        tl[i][tx] = h0[(size_t)(h0t + i) * B_D + b0 + tx];
    __syncthreads();
    for (int i = ty; i < 32; i += 8) {
        __nv_bfloat16 hh, ll;
        bsplit(tl[tx][i], hh, ll);
        size_t o = (size_t)(b0 + i) * KT + h0t + tx;
        g_h0Th[o] = hh; g_h0Tl[o] = ll;
    }
}

__global__ void k_init(const float* __restrict__ c0)
{
    int i = blockIdx.x * 256 + threadIdx.x;
    if (i < HB) g_c[i] = c0[i];
    if (i == 0) g_barcnt = 0u;
}

__global__ void __launch_bounds__(256)
k_tiC0(const float* __restrict__ t0)
{
    __shared__ float sm[2 * 16 * 128];
    int m0 = blockIdx.y * 128, n0 = blockIdx.x * 128;
    float acc[8][8] = {};
    gk128(g_wtiT, t0, H_D, TI_M, B_D, m0, n0, acc, sm);
    int tx = threadIdx.x % 16, ty = threadIdx.x / 16;
#pragma unroll
    for (int i = 0; i < 8; i++) {
        int m = m0 + ty * 8 + i;
        size_t idx = (size_t)m * B_D + n0 + tx * 8;
        *(float4*)&g_tiC[idx]     = make_float4(acc[i][0], acc[i][1], acc[i][2], acc[i][3]);
        *(float4*)&g_tiC[idx + 4] = make_float4(acc[i][4], acc[i][5], acc[i][6], acc[i][7]);
    }
}

// ---------------- generic wmma GEMM against g_bT (unchanged) ----------------
template <int MODE>
__global__ void __launch_bounds__(256)
k_wm(const float* __restrict__ bi, float* __restrict__ out)
{
    constexpr int KTOT = MODE ? KT : KE;
    constexpr int BOFS = MODE ? 0 : 512;
    constexpr int LDA  = MODE ? KT : KE;
    __shared__ float es[8][320];
    const int t = MODE ? blockIdx.z : blockIdx.z + 1;
    const int tb = MODE ? t : t - 1;
    const int m0 = blockIdx.x * 128, n0 = blockIdx.y * 128;
    const int wid = threadIdx.x / 32, lane = threadIdx.x % 32;
    const int wr = wid >> 2, wc = wid & 3;
    const __nv_bfloat16* Ah = (MODE ? g_AtsH : g_AtcH) + (size_t)(m0 + wr * 64) * LDA;
    const __nv_bfloat16* Al = (MODE ? g_AtsL : g_AtcL) + (size_t)(m0 + wr * 64) * LDA;
    const __nv_bfloat16* Bh = g_bTh + ((size_t)tb * B_D + n0 + wc * 32) * KT + BOFS;
    const __nv_bfloat16* Bl = g_bTl + ((size_t)tb * B_D + n0 + wc * 32) * KT + BOFS;

    wmma::fragment<wmma::accumulator, 16, 16, 16, float> acc[4][2];
#pragma unroll
    for (int i = 0; i < 4; i++)
#pragma unroll
        for (int j = 0; j < 2; j++) wmma::fill_fragment(acc[i][j], 0.f);

    for (int kk = 0; kk < KTOT; kk += 16) {
        wmma::fragment<wmma::matrix_b, 16, 16, 16, __nv_bfloat16, wmma::col_major> bh[2], bl[2];
#pragma unroll
        for (int j = 0; j < 2; j++) {
            wmma::load_matrix_sync(bh[j], Bh + (size_t)j * 16 * KT + kk, KT);
            wmma::load_matrix_sync(bl[j], Bl + (size_t)j * 16 * KT + kk, KT);
        }
#pragma unroll
        for (int i = 0; i < 4; i++) {
            wmma::fragment<wmma::matrix_a, 16, 16, 16, __nv_bfloat16, wmma::row_major> ah, al;
            wmma::load_matrix_sync(ah, Ah + (size_t)i * 16 * LDA + kk, LDA);
            wmma::load_matrix_sync(al, Al + (size_t)i * 16 * LDA + kk, LDA);
#pragma unroll
            for (int j = 0; j < 2; j++) {
                wmma::mma_sync(acc[i][j], ah, bh[j], acc[i][j]);
                wmma::mma_sync(acc[i][j], ah, bl[j], acc[i][j]);
                wmma::mma_sync(acc[i][j], al, bh[j], acc[i][j]);
            }
        }
    }

#pragma unroll 1
    for (int i = 0; i < 4; i++)
#pragma unroll 1
        for (int j = 0; j < 2; j++) {
            wmma::store_matrix_sync(&es[wid][0], acc[i][j], 20, wmma::mem_row_major);
            __syncwarp();
            int m = m0 + wr * 64 + i * 16, b = n0 + wc * 32 + j * 16;
            int r0 = lane >> 1, c0 = (lane & 1) * 8;
            if (MODE == 0) {
                float add = bi[m + r0];
                float v[8];
#pragma unroll
                for (int q = 0; q < 8; q++) v[q] = es[wid][r0 * 20 + c0 + q] + add;
                float* dst = &g_tiC[((size_t)t * TI_M + m + r0) * B_D + b + c0];
                *(float4*)dst       = make_float4(v[0], v[1], v[2], v[3]);
                *(float4*)(dst + 4) = make_float4(v[4], v[5], v[6], v[7]);
            } else {
                float add = bi[4 * H_D + m + r0];
                float v[8];
#pragma unroll
                for (int q = 0; q < 8; q++) v[q] = es[wid][r0 * 20 + c0 + q] + add;
                float* dst = &g_Ts[((size_t)t * H_D + m + r0) * B_D + b + c0];
                *(float4*)dst       = make_float4(v[0], v[1], v[2], v[3]);
                *(float4*)(dst + 4) = make_float4(v[4], v[5], v[6], v[7]);
                __syncwarp();
                int bc = lane & 15, mh = (lane >> 4) * 8;
                float w[8];
#pragma unroll
                for (int q = 0; q < 8; q++)
                    w[q] = es[wid][(mh + q) * 20 + bc] + bi[4 * H_D + m + mh + q];
                float* od = &out[OFF_TS + ((size_t)(b + bc) * T_STEPS + t) * H_D + m + mh];
                *(float4*)od       = make_float4(w[0], w[1], w[2], w[3]);
                *(float4*)(od + 4) = make_float4(w[4], w[5], w[6], w[7]);
            }
            __syncwarp();
        }
}

// ------------------------------ phase A ------------------------------------
__global__ void __launch_bounds__(256, 2)
k_x(const float* __restrict__ inputs, const float* __restrict__ lms,
    const float* __restrict__ poses, const float* __restrict__ caps,
    const float* __restrict__ w_lmw, const float* __restrict__ w_posw,
    const float* __restrict__ w_capw)
{
    __shared__ float sm[2 * 16 * 128];
    int t = blockIdx.z, m0 = blockIdx.y * 128, n0 = blockIdx.x * 128;
    float acc[8][8] = {};
    gk128(w_lmw,  lms   + (size_t)t * LM_D  * B_D, LM_D,  IN_D, B_D, m0, n0, acc, sm);
    gk128(w_posw, poses + (size_t)t * POS_D * B_D, POS_D, IN_D, B_D, m0, n0, acc, sm);
    gk128(w_capw, caps  + (size_t)t * CAP_D * B_D, CAP_D, IN_D, B_D, m0, n0, acc, sm);
    int tx = threadIdx.x % 16, ty = threadIdx.x / 16;
    size_t base = (size_t)t * IN_D * B_D;
    float xv[8][8];
#pragma unroll
    for (int i = 0; i < 8; i++) {
        size_t idx = base + (size_t)(m0 + ty * 8 + i) * B_D + n0 + tx * 8;
#pragma unroll
        for (int q = 0; q < 2; q++) {
            float4 v = *(const float4*)&inputs[idx + q * 4];
            xv[i][q*4+0] = acc[i][q*4+0] + v.x; xv[i][q*4+1] = acc[i][q*4+1] + v.y;
            xv[i][q*4+2] = acc[i][q*4+2] + v.z; xv[i][q*4+3] = acc[i][q*4+3] + v.w;
        }
    }
#pragma unroll
    for (int j = 0; j < 8; j++) {
        int b = n0 + tx * 8 + j;
        __align__(16) __nv_bfloat16 ah[8], al[8];
#pragma unroll
        for (int i = 0; i < 8; i++) bsplit(xv[i][j], ah[i], al[i]);
        size_t o = ((size_t)t * B_D + b) * IN_D + m0 + ty * 8;
        *(uint4*)&g_xTh[o] = *(uint4*)ah;
        *(uint4*)&g_xTl[o] = *(uint4*)al;
    }
}

// -------- wmma k_ii (unchanged) --------
#define LDS_K 40
__global__ void __launch_bounds__(256)
k_ii_wm(const float* __restrict__ b_i)
{
    extern __shared__ char dsm[];
    __nv_bfloat16 (*Ah)[LDS_K] = (__nv_bfloat16 (*)[LDS_K])(dsm);
    __nv_bfloat16 (*Al)[LDS_K] = (__nv_bfloat16 (*)[LDS_K])(dsm + 10240);
    __nv_bfloat16 (*Bh)[LDS_K] = (__nv_bfloat16 (*)[LDS_K])(dsm + 20480);
    __nv_bfloat16 (*Bl)[LDS_K] = (__nv_bfloat16 (*)[LDS_K])(dsm + 30720);

    const int t = blockIdx.z, m0 = blockIdx.x * 128, n0 = blockIdx.y * 128;
    const int tid = threadIdx.x, wid = tid / 32, lane = tid % 32;
    const int wr = wid >> 2, wc = wid & 3;

    wmma::fragment<wmma::accumulator, 16, 16, 16, float> acc[4][2];
#pragma unroll
    for (int i = 0; i < 4; i++)
#pragma unroll
        for (int j = 0; j < 2; j++) wmma::fill_fragment(acc[i][j], 0.f);

    const __nv_bfloat16* wh = g_wiih + (size_t)m0 * IN_D;
    const __nv_bfloat16* wl = g_wiil + (size_t)m0 * IN_D;
    const __nv_bfloat16* xh = g_xTh + ((size_t)t * B_D + n0) * IN_D;
    const __nv_bfloat16* xl = g_xTl + ((size_t)t * B_D + n0) * IN_D;

    for (int ch = 0; ch < 16; ch++) {
#pragma unroll
        for (int it = 0; it < 2; it++) {
            int s = tid + it * 256, r = s >> 2, kq = (s & 3) * 8;
            *(uint4*)&Ah[r][kq] = *(const uint4*)(wh + (size_t)r * IN_D + ch * 32 + kq);
            *(uint4*)&Al[r][kq] = *(const uint4*)(wl + (size_t)r * IN_D + ch * 32 + kq);
            *(uint4*)&Bh[r][kq] = *(const uint4*)(xh + (size_t)r * IN_D + ch * 32 + kq);
            *(uint4*)&Bl[r][kq] = *(const uint4*)(xl + (size_t)r * IN_D + ch * 32 + kq);
        }
        __syncthreads();
#pragma unroll
        for (int kk = 0; kk < 2; kk++) {
            wmma::fragment<wmma::matrix_b, 16, 16, 16, __nv_bfloat16, wmma::col_major> bh[2], bl[2];
#pragma unroll
            for (int j = 0; j < 2; j++) {
                wmma::load_matrix_sync(bh[j], &Bh[wc * 32 + j * 16][kk * 16], LDS_K);
                wmma::load_matrix_sync(bl[j], &Bl[wc * 32 + j * 16][kk * 16], LDS_K);
            }
#pragma unroll
            for (int i = 0; i < 4; i++) {
                wmma::fragment<wmma::matrix_a, 16, 16, 16, __nv_bfloat16, wmma::row_major> ah, al;
                wmma::load_matrix_sync(ah, &Ah[wr * 64 + i * 16][kk * 16], LDS_K);
                wmma::load_matrix_sync(al, &Al[wr * 64 + i * 16][kk * 16], LDS_K);
#pragma unroll
                for (int j = 0; j < 2; j++) {
                    wmma::mma_sync(acc[i][j], ah, bh[j], acc[i][j]);
                    wmma::mma_sync(acc[i][j], ah, bl[j], acc[i][j]);
                    wmma::mma_sync(acc[i][j], al, bh[j], acc[i][j]);
                }
            }
        }
        __syncthreads();
    }

    float (*eb)[20] = (float (*)[20])(dsm + wid * 1280);
    size_t preb = (size_t)t * GATE_M * B_D;
    size_t tib  = (size_t)t * TI_M * B_D;
#pragma unroll 1
    for (int i = 0; i < 4; i++)
#pragma unroll 1
        for (int j = 0; j < 2; j++) {
            wmma::store_matrix_sync(&eb[0][0], acc[i][j], 20, wmma::mem_row_major);
            __syncwarp();
            int r0 = lane >> 1, c0 = (lane & 1) * 8;
            int p = m0 + wr * 64 + i * 16 + r0;
            int b = n0 + wc * 32 + j * 16 + c0;
            int g = p & 3, rr = p >> 2;
            float add = b_i[g * H_D + rr];
            float v[8];
#pragma unroll
            for (int q = 0; q < 8; q++) v[q] = eb[r0][c0 + q] + add;
            if (g < 3) {
                const float* tc = &g_tiC[tib + (size_t)(g * H_D + rr) * B_D + b];
#pragma unroll
                for (int q = 0; q < 8; q++) v[q] += tc[q];
            }
            float* dst = &g_pre[preb + (size_t)p * B_D + b];
            *(float4*)dst       = make_float4(v[0], v[1], v[2], v[3]);
            *(float4*)(dst + 4) = make_float4(v[4], v[5], v[6], v[7]);
            __syncwarp();
        }
}

// --------------------- persistent serial loop ------------------------------
__device__ __forceinline__ void grid_bar(unsigned target)
{
    __syncthreads();
    if (threadIdx.x == 0) {
        __threadfence();
        atomicAdd(&g_barcnt, 1u);
        while (*((volatile unsigned*)&g_barcnt) < target) __nanosleep(64);
    }
    __syncthreads();
    __threadfence();
}

#define LD2 72
__global__ void __launch_bounds__(256)
k_loop()
{
    __shared__ __align__(16) char lsm[36864];
    __nv_bfloat16 (*Ah)[LD2] = (__nv_bfloat16 (*)[LD2])(lsm);
    __nv_bfloat16 (*Al)[LD2] = (__nv_bfloat16 (*)[LD2])(lsm + 9216);
    __nv_bfloat16 (*Bh)[LD2] = (__nv_bfloat16 (*)[LD2])(lsm + 18432);
    __nv_bfloat16 (*Bl)[LD2] = (__nv_bfloat16 (*)[LD2])(lsm + 27648);
    float* fsm = (float*)lsm;

    const int cta = blockIdx.x;
    const int tid = threadIdx.x, wid = tid / 32, lane = tid % 32;
    const int tx = tid % 16, ty = tid / 16;
    const int m0 = (cta >> 2) * 64, n0 = (cta & 3) * 64;   // phase-1 tile
    const int wr = wid >> 1, wc = wid & 1;                  // 4x2 warp grid
    unsigned gen = 0;

    for (int t = 0; t < T_STEPS; t++) {
        const __nv_bfloat16* hTh = (t == 0) ? g_h0Th : (g_bTh + (size_t)(t - 1) * B_D * KT);
        const __nv_bfloat16* hTl = (t == 0) ? g_h0Tl : (g_bTl + (size_t)(t - 1) * B_D * KT);

        // ---- phase 1: Wf@h (wmma, 3-product) + fused gates ----
        wmma::fragment<wmma::accumulator, 16, 16, 16, float> acc[2];
        wmma::fill_fragment(acc[0], 0.f);
        wmma::fill_fragment(acc[1], 0.f);

        for (int ch = 0; ch < 8; ch++) {
#pragma unroll
            for (int it = 0; it < 2; it++) {
                int s = tid + it * 256, r = s >> 3, c8 = (s & 7) * 8;
                *(uint4*)&Ah[r][c8] = *(const uint4*)&g_wfh[(size_t)(m0 + r) * H_D + ch * 64 + c8];
                *(uint4*)&Al[r][c8] = *(const uint4*)&g_wfl[(size_t)(m0 + r) * H_D + ch * 64 + c8];
                *(uint4*)&Bh[r][c8] = *(const uint4*)&hTh[(size_t)(n0 + r) * KT + ch * 64 + c8];
                *(uint4*)&Bl[r][c8] = *(const uint4*)&hTl[(size_t)(n0 + r) * KT + ch * 64 + c8];
            }
            __syncthreads();
#pragma unroll
            for (int kk = 0; kk < 4; kk++) {
                wmma::fragment<wmma::matrix_a, 16, 16, 16, __nv_bfloat16, wmma::row_major> ah, al;
                wmma::load_matrix_sync(ah, &Ah[wr * 16][kk * 16], LD2);
                wmma::load_matrix_sync(al, &Al[wr * 16][kk * 16], LD2);
#pragma unroll
                for (int j = 0; j < 2; j++) {
                    wmma::fragment<wmma::matrix_b, 16, 16, 16, __nv_bfloat16, wmma::col_major> bh, bl;
                    wmma::load_matrix_sync(bh, &Bh[wc * 32 + j * 16][kk * 16], LD2);
                    wmma::load_matrix_sync(bl, &Bl[wc * 32 + j * 16][kk * 16], LD2);
                    wmma::mma_sync(acc[j], ah, bh, acc[j]);
                    wmma::mma_sync(acc[j], ah, bl, acc[j]);
                    wmma::mma_sync(acc[j], al, bh, acc[j]);
                }
            }
            __syncthreads();
        }
        // stage accumulators, then gate math (g_pre carries ii + tiC + bias)
        float* ew = fsm + wid * 640;   // 16 x 40
        wmma::store_matrix_sync(ew, acc[0], 40, wmma::mem_row_major);
        wmma::store_matrix_sync(ew + 16, acc[1], 40, wmma::mem_row_major);
        __syncwarp();
        {
            int rl = lane >> 3, bg = lane & 7;
            int r = ((m0 + wr * 16) >> 2) + rl;
            int colw = wc * 32 + bg * 4;
            int b = n0 + colw;
            int cw = bg * 4;  // col within warp's staging (32 cols)
            size_t preb = (size_t)t * GATE_M * B_D + (size_t)(m0 + wr * 16 + rl * 4) * B_D + b;
            float4 pi4 = *(const float4*)&g_pre[preb];
            float4 pf4 = *(const float4*)&g_pre[preb + B_D];
            float4 pz4 = *(const float4*)&g_pre[preb + 2 * B_D];
            float4 po4 = *(const float4*)&g_pre[preb + 3 * B_D];
            float4 co4 = *(const float4*)&g_c[r * B_D + b];
            float pia[4] = {pi4.x, pi4.y, pi4.z, pi4.w}, pfa[4] = {pf4.x, pf4.y, pf4.z, pf4.w};
            float pza[4] = {pz4.x, pz4.y, pz4.z, pz4.w}, poa[4] = {po4.x, po4.y, po4.z, po4.w};
            float coa[4] = {co4.x, co4.y, co4.z, co4.w};
            float cn[4], op[4];
#pragma unroll
            for (int q = 0; q < 4; q++) {
                float ig = sigm(ew[(rl * 4 + 0) * 40 + cw + q] + pia[q]);
                float fg = sigm(ew[(rl * 4 + 1) * 40 + cw + q] + pfa[q]);
                float zg = tanhf(ew[(rl * 4 + 2) * 40 + cw + q] + pza[q]);
                cn[q] = fg * coa[q] + ig * zg;
                op[q] = ew[(rl * 4 + 3) * 40 + cw + q] + poa[q];
            }
            *(float4*)&g_c[r * B_D + b]    = make_float4(cn[0], cn[1], cn[2], cn[3]);
            *(float4*)&g_opre[r * B_D + b] = make_float4(op[0], op[1], op[2], op[3]);
        }
        grid_bar(++gen * NCTA);

        // ---- phase 2: o gate + h, write bf16-split h^T into g_bT ----
        {
            int m20 = (cta >> 3) * 32, n20 = (cta & 7) * 32;
            float acc2[2][2] = {};
            gk<32,32,32,2,2>(g_wcoT, g_c, H_D, H_D, B_D, m20, n20, acc2, fsm);
            float (*hs)[33] = (float (*)[33])fsm;
#pragma unroll
            for (int i = 0; i < 2; i++)
#pragma unroll
                for (int j = 0; j < 2; j++) {
                    int lr = ty * 2 + i, lb = tx * 2 + j;
                    int rb = (m20 + lr) * B_D + n20 + lb;
                    float o = sigm(acc2[i][j] + g_opre[rb]);
                    hs[lr][lb] = o * tanhf(g_c[rb]);
                }
            __syncthreads();
            {
                int r2 = tid >> 3, c4 = (tid & 7) * 4;
                __nv_bfloat16 hh[4], ll[4];
#pragma unroll
                for (int q = 0; q < 4; q++) bsplit(hs[c4 + q][r2], hh[q], ll[q]);
                size_t o = ((size_t)t * B_D + n20 + r2) * KT + m20 + c4;
                *(uint2*)&g_bTh[o] = *(uint2*)hh;
                *(uint2*)&g_bTl[o] = *(uint2*)ll;
            }
        }
        grid_bar(++gen * NCTA);
    }
}

// ------------------------------ k_y (unchanged) -----------------------------
__global__ void __launch_bounds__(256)
k_y(const float* __restrict__ byf, const float* __restrict__ byc, float* __restrict__ out)
{
    __shared__ float sm[2 * 64 * 68];
    int t = blockIdx.y, n0 = blockIdx.x * 64;
    const float* Tst = g_Ts + (size_t)t * HB;
    float aF[4][4] = {}, aC[4][4] = {};
    gk<64,64,16,4,4>(g_wyfT, Tst, H_D, TAG, B_D, 0, n0, aF, sm);
    gk<64,64,16,4,4>(g_wycT, Tst, H_D, TAG, B_D, 0, n0, aC, sm);
    float (*yF)[68] = (float (*)[68])sm;
    float (*yC)[68] = (float (*)[68])(sm + 64 * 68);
    int tx = threadIdx.x % 16, ty = threadIdx.x / 16;
#pragma unroll
    for (int i = 0; i < 4; i++)
#pragma unroll
        for (int j = 0; j < 4; j++) {
            int m = ty * 4 + i, n = tx * 4 + j;
            yF[m][n] = aF[i][j] + byf[m];
            yC[m][n] = aC[i][j] + byc[m];
        }
    __syncthreads();
    if (threadIdx.x < 64) {
        int col = threadIdx.x, b = n0 + col;
        float mxF = -1e30f, mxC = -1e30f;
#pragma unroll
        for (int m = 0; m < TAG; m++) {
            mxF = fmaxf(mxF, yF[m][col]);
            mxC = fmaxf(mxC, yC[m][col]);
        }
        float sF = 0.f, sC = 0.f;
#pragma unroll
        for (int m = 0; m < TAG; m++) {
            sF += expf(yF[m][col] - mxF);
            sC += expf(yC[m][col] - mxC);
        }
        float lseF = mxF + logf(sF), lseC = mxC + logf(sC);
        size_t base = ((size_t)b * T_STEPS + t) * TAG;
#pragma unroll
        for (int m = 0; m < TAG; m++) {
            float vf = yF[m][col], vc = yC[m][col];
            out[OFF_LF + base + m] = vf - lseF;
            out[OFF_LC + base + m] = vc - lseC;
            out[OFF_YF + base + m] = vf;
            out[OFF_YC + base + m] = vc;
        }
    }
}

// ------------------------------- launch ------------------------------------
extern "C" void kernel_launch(void* const* d_in, const int* in_sizes, int n_in,
                              void* d_out, int out_size)
{
    const float* inputs   = (const float*)d_in[0];
    const float* lms      = (const float*)d_in[1];
    const float* poses    = (const float*)d_in[2];
    const float* caps     = (const float*)d_in[3];
    const float* h0       = (const float*)d_in[4];
    const float* c0       = (const float*)d_in[5];
    const float* t0       = (const float*)d_in[6];
    const float* w_ii     = (const float*)d_in[7];
    const float* w_hi     = (const float*)d_in[8];
    const float* w_ti     = (const float*)d_in[9];
    const float* w_co     = (const float*)d_in[10];
    const float* w_ht     = (const float*)d_in[11];
    const float* b_i      = (const float*)d_in[12];
    const float* b_y_fact = (const float*)d_in[14];
    const float* b_y_cond = (const float*)d_in[16];
    const float* w_lmw    = (const float*)d_in[17];
    const float* w_posw   = (const float*)d_in[18];
    const float* w_capw   = (const float*)d_in[19];
    const float* w_lmt    = (const float*)d_in[20];
    const float* w_post   = (const float*)d_in[21];
    const float* w_capt   = (const float*)d_in[22];
    float* out = (float*)d_out;

    float *pwti, *pwco, *pyf, *pyc, *pvc;
    cudaGetSymbolAddress((void**)&pwti, g_wtiT);
    cudaGetSymbolAddress((void**)&pwco, g_wcoT);
    cudaGetSymbolAddress((void**)&pyf,  g_wyfT);
    cudaGetSymbolAddress((void**)&pyc,  g_wycT);
    cudaGetSymbolAddress((void**)&pvc,  g_vc);
    dim3 tb(32, 8);

    k_embT <<<dim3(8, T_STEPS), tb>>>(lms, poses, caps);
    k_tr   <<<dim3(16, 48), tb>>>(w_ti, pwti, TI_M, H_D);
    k_small<<<(TI_M * (KE + 1) + 255) / 256, 256>>>(w_lmt, w_post, w_capt, b_i);
    k_tiC0 <<<dim3(2, 12), 256>>>(t0);
    k_permii<<<(GATE_M * IN_D) / 256, 256>>>(w_ii);
    k_wm<0><<<dim3(12, 2, T_STEPS - 1), 256>>>(pvc, nullptr);
    k_x    <<<dim3(2, 4, T_STEPS), 256>>>(inputs, lms, poses, caps, w_lmw, w_posw, w_capw);
    k_ii_wm<<<dim3(16, 2, T_STEPS), 256, 40960>>>(b_i);

    k_tr   <<<dim3(16, 16), tb>>>(w_co, pwco, H_D, H_D);
    k_w2   <<<dim3(8, 24), 256>>>(w_hi, w_ht);
    k_fillo<<<1024, 256>>>(w_hi);
    k_init <<<HB / 256, 256>>>(c0);
    k_h0T  <<<dim3(8, 16), tb>>>(h0);
    k_Ats  <<<(H_D * KT + 255) / 256, 256>>>(w_ht, w_lmt, w_post, w_capt);

    k_loop <<<NCTA, 256>>>();

    k_wm<1><<<dim3(4, 2, T_STEPS), 256>>>(b_i, out);
    k_tr   <<<dim3(16, 2), tb>>>((const float*)d_in[13], pyf, TAG, H_D);
    k_tr   <<<dim3(16, 2), tb>>>((const float*)d_in[15], pyc, TAG, H_D);
    k_y    <<<dim3(4, T_STEPS), 256>>>(b_y_fact, b_y_cond, out);
}